// round 1
// baseline (speedup 1.0000x reference)
#include <cuda_runtime.h>
#include <math.h>

#define NN 50000
#define EE 800000
#define FULLM 0xffffffffu

// ---------------- static scratch (no allocation allowed) ----------------
__device__ __align__(128) float g_bufA[NN * 256];   // gemm outputs / Ht (ld 224)
__device__ __align__(128) float g_bufB[NN * 256];   // aggregated outputs
__device__ float g_as[NN * 8];
__device__ float g_ad[NN * 8];
__device__ float g_as4[NN * 4];
__device__ float g_ad4[NN * 4];
__device__ __align__(128) float g_Wcat[256 * 224];
__device__ float g_acs[224];
__device__ float g_acd[224];
__device__ float g_bc[224];
__device__ int g_deg[NN];
__device__ int g_rowp[NN + 1];
__device__ int g_cursor[NN];
__device__ int g_col[EE];

// ---------------- helpers ----------------
__device__ __forceinline__ float wredsum(float v) {
#pragma unroll
    for (int o = 16; o > 0; o >>= 1) v += __shfl_xor_sync(FULLM, v, o);
    return v;
}
__device__ __forceinline__ float wredmax(float v) {
#pragma unroll
    for (int o = 16; o > 0; o >>= 1) v = fmaxf(v, __shfl_xor_sync(FULLM, v, o));
    return v;
}
__device__ __forceinline__ float lrelu(float e) { return e > 0.f ? e : 0.2f * e; }

// ---------------- CSR build ----------------
__global__ void zero_int(int* p, int n) {
    int i = blockIdx.x * blockDim.x + threadIdx.x;
    if (i < n) p[i] = 0;
}
__global__ void copy_int(const int* __restrict__ s, int* __restrict__ d, int n) {
    int i = blockIdx.x * blockDim.x + threadIdx.x;
    if (i < n) d[i] = s[i];
}
__global__ void count_deg(const int* __restrict__ ei, int E, int* deg) {
    int e = blockIdx.x * blockDim.x + threadIdx.x;
    if (e < E) atomicAdd(&deg[ei[E + e]], 1);
}
__global__ void scan_block(const int* __restrict__ deg, int* __restrict__ rowp, int n) {
    __shared__ int sm[1024];
    int tid = threadIdx.x;
    int chunk = (n + 1023) >> 10;
    int start = tid * chunk;
    int s = 0;
    for (int i = 0; i < chunk; i++) { int id = start + i; if (id < n) s += deg[id]; }
    sm[tid] = s; __syncthreads();
    for (int o = 1; o < 1024; o <<= 1) {
        int t = (tid >= o) ? sm[tid - o] : 0;
        __syncthreads();
        sm[tid] += t;
        __syncthreads();
    }
    int run = sm[tid] - s;
    for (int i = 0; i < chunk; i++) {
        int id = start + i;
        if (id < n) { rowp[id] = run; run += deg[id]; }
    }
    if (tid == 1023) rowp[n] = sm[1023];
}
__global__ void fill_col(const int* __restrict__ ei, int E, int* cursor, int* __restrict__ col) {
    int e = blockIdx.x * blockDim.x + threadIdx.x;
    if (e < E) {
        int s = ei[e];
        int d = ei[E + e];
        int p = atomicAdd(&cursor[d], 1);
        col[p] = s;
    }
}

// ---------------- SGEMM 128x128x16, 8x8 microtile ----------------
// C[M,N] = A[M,K] * B[K,N], all row-major, lda=K, ldb=ldc=N (N multiple of 4, K multiple of 16)
__global__ __launch_bounds__(256, 2) void sgemm128(
    const float* __restrict__ A, const float* __restrict__ B, float* __restrict__ C,
    int M, int N, int K) {
    __shared__ float As[16][128];
    __shared__ float Bs[16][128];
    int tid = threadIdx.x;
    int tx = tid & 15, ty = tid >> 4;
    int rowBase = blockIdx.y * 128;
    int colBase = blockIdx.x * 128;
    float acc[8][8];
#pragma unroll
    for (int i = 0; i < 8; i++)
#pragma unroll
        for (int j = 0; j < 8; j++) acc[i][j] = 0.f;

    for (int kt = 0; kt < K; kt += 16) {
#pragma unroll
        for (int i = 0; i < 2; i++) {
            int s = tid + i * 256;
            int r = s >> 2, c4 = (s & 3) << 2;
            float4 v = make_float4(0.f, 0.f, 0.f, 0.f);
            int gr = rowBase + r;
            if (gr < M) v = *(const float4*)(A + (size_t)gr * K + kt + c4);
            As[c4 + 0][r] = v.x; As[c4 + 1][r] = v.y; As[c4 + 2][r] = v.z; As[c4 + 3][r] = v.w;
        }
#pragma unroll
        for (int i = 0; i < 2; i++) {
            int s = tid + i * 256;
            int r = s >> 5, c4 = (s & 31) << 2;
            float4 v = make_float4(0.f, 0.f, 0.f, 0.f);
            int gc = colBase + c4;
            if (gc < N) v = *(const float4*)(B + (size_t)(kt + r) * N + gc);
            *(float4*)&Bs[r][c4] = v;
        }
        __syncthreads();
#pragma unroll
        for (int k = 0; k < 16; k++) {
            float a[8], b[8];
#pragma unroll
            for (int i = 0; i < 8; i++) a[i] = As[k][ty * 8 + i];
#pragma unroll
            for (int j = 0; j < 8; j++) b[j] = Bs[k][tx * 8 + j];
#pragma unroll
            for (int i = 0; i < 8; i++)
#pragma unroll
                for (int j = 0; j < 8; j++) acc[i][j] = fmaf(a[i], b[j], acc[i][j]);
        }
        __syncthreads();
    }
#pragma unroll
    for (int i = 0; i < 8; i++) {
        int gr = rowBase + ty * 8 + i;
        if (gr >= M) continue;
#pragma unroll
        for (int j = 0; j < 8; j += 4) {
            int gc = colBase + tx * 8 + j;
            if (gc < N) {
                float4 v = make_float4(acc[i][j], acc[i][j + 1], acc[i][j + 2], acc[i][j + 3]);
                *(float4*)(C + (size_t)gr * N + gc) = v;
            }
        }
    }
}

// ---------------- per-node attention scalars (conv, 8 heads x 32 ch) ----------------
__global__ void alpha_conv(const float* __restrict__ h, const float* __restrict__ a_s,
                           const float* __restrict__ a_d, float* __restrict__ as_out,
                           float* __restrict__ ad_out, int n) {
    int warp = (blockIdx.x * blockDim.x + threadIdx.x) >> 5;
    int lane = threadIdx.x & 31;
    if (warp >= n) return;
    const float* row = h + (size_t)warp * 256;
#pragma unroll
    for (int k = 0; k < 8; k++) {
        float v = row[k * 32 + lane];
        float s = v * a_s[k * 32 + lane];
        float d = v * a_d[k * 32 + lane];
        s = wredsum(s); d = wredsum(d);
        if (lane == 0) { as_out[warp * 8 + k] = s; ad_out[warp * 8 + k] = d; }
    }
}

// ---------------- GAT aggregation (conv layers, 8 heads x 32 ch) ----------------
__global__ void gat_agg_conv(const float* __restrict__ h, const float* __restrict__ asv,
                             const float* __restrict__ adv, const int* __restrict__ rowp,
                             const int* __restrict__ col, const float* __restrict__ bias,
                             float* __restrict__ out, int n, int do_elu) {
    int warp = (blockIdx.x * blockDim.x + threadIdx.x) >> 5;
    int lane = threadIdx.x & 31;
    if (warp >= n) return;
    int node = warp;
    float asn = 0.f, adn = 0.f;
    if (lane < 8) { asn = asv[node * 8 + lane]; adn = adv[node * 8 + lane]; }
    float adh[8], mh[8];
#pragma unroll
    for (int k = 0; k < 8; k++) {
        adh[k] = __shfl_sync(FULLM, adn, k);
        mh[k] = lrelu(__shfl_sync(FULLM, asn, k) + adh[k]);   // self-loop e initializes max
    }
    int beg = rowp[node], end = rowp[node + 1];
    // pass A: per-head max (lane-parallel over edges)
    for (int i = beg + lane; i < end; i += 32) {
        int src = col[i];
        const float* ap = asv + src * 8;
#pragma unroll
        for (int k = 0; k < 8; k++) mh[k] = fmaxf(mh[k], lrelu(ap[k] + adh[k]));
    }
#pragma unroll
    for (int k = 0; k < 8; k++) mh[k] = wredmax(mh[k]);
    float m_mine = mh[0];
#pragma unroll
    for (int k = 1; k < 8; k++) if (lane == k) m_mine = mh[k];
    // pass B: weighted accumulation
    float acc[8];
#pragma unroll
    for (int k = 0; k < 8; k++) acc[k] = 0.f;
    float ssum = 0.f;
    {   // self loop
        float w = 0.f;
        if (lane < 8) { w = expf(lrelu(asn + adn) - m_mine); ssum += w; }
        const float* hs = h + (size_t)node * 256;
#pragma unroll
        for (int k = 0; k < 8; k++) acc[k] += __shfl_sync(FULLM, w, k) * hs[k * 32 + lane];
    }
    for (int i = beg; i < end; ++i) {
        int src = col[i];
        float w = 0.f;
        if (lane < 8) { w = expf(lrelu(asv[src * 8 + lane] + adn) - m_mine); ssum += w; }
        const float* hs = h + (size_t)src * 256;
#pragma unroll
        for (int k = 0; k < 8; k++) acc[k] += __shfl_sync(FULLM, w, k) * hs[k * 32 + lane];
    }
#pragma unroll
    for (int k = 0; k < 8; k++) {
        float denom = __shfl_sync(FULLM, ssum, k) + 1e-16f;
        float v = acc[k] / denom + bias[k * 32 + lane];
        if (do_elu) v = v > 0.f ? v : expm1f(v);
        out[(size_t)node * 256 + k * 32 + lane] = v;
    }
}

// ---------------- pack 4 task weight matrices / attn vectors / biases ----------------
__global__ void pack_task(const float* __restrict__ W0, const float* __restrict__ W1,
                          const float* __restrict__ W2, const float* __restrict__ W3,
                          const float* __restrict__ s0, const float* __restrict__ s1,
                          const float* __restrict__ s2, const float* __restrict__ s3,
                          const float* __restrict__ d0, const float* __restrict__ d1,
                          const float* __restrict__ d2, const float* __restrict__ d3,
                          const float* __restrict__ b0, const float* __restrict__ b1,
                          const float* __restrict__ b2, const float* __restrict__ b3,
                          float* __restrict__ Wcat, float* __restrict__ acs,
                          float* __restrict__ acd, float* __restrict__ bc) {
    int idx = blockIdx.x * blockDim.x + threadIdx.x;
    if (idx >= 256 * 224) return;
    int k = idx / 224, j = idx % 224;
    float v = 0.f;
    if (j < 12) v = W0[k * 12 + j];
    else if (j < 42) v = W1[k * 30 + (j - 12)];
    else if (j < 102) v = W2[k * 60 + (j - 42)];
    else if (j < 222) v = W3[k * 120 + (j - 102)];
    Wcat[idx] = v;
    if (k == 0) {
        float s = 0.f, d = 0.f, b = 0.f;
        if (j < 12)       { s = s0[j];        d = d0[j];        b = b0[j]; }
        else if (j < 42)  { s = s1[j - 12];   d = d1[j - 12];   b = b1[j - 12]; }
        else if (j < 102) { s = s2[j - 42];   d = d2[j - 42];   b = b2[j - 42]; }
        else if (j < 222) { s = s3[j - 102];  d = d3[j - 102];  b = b3[j - 102]; }
        acs[j] = s; acd[j] = d; bc[j] = b;
    }
}

// ---------------- per-node attention scalars (4 task heads) ----------------
__global__ void alpha_task(const float* __restrict__ Ht, const float* __restrict__ acs,
                           const float* __restrict__ acd, float* __restrict__ as4,
                           float* __restrict__ ad4, int n) {
    int warp = (blockIdx.x * blockDim.x + threadIdx.x) >> 5;
    int lane = threadIdx.x & 31;
    if (warp >= n) return;
    const float* row = Ht + (size_t)warp * 224;
    float s0 = 0, s1 = 0, s2 = 0, s3 = 0, d0 = 0, d1 = 0, d2 = 0, d3 = 0;
#pragma unroll
    for (int k = 0; k < 7; k++) {
        int c = lane + 32 * k;
        float hv = row[c];
        float vs = hv * acs[c], vd = hv * acd[c];   // pad channels have acs=acd=0
        int t = (c >= 12) + (c >= 42) + (c >= 102);
        if (t == 0) { s0 += vs; d0 += vd; }
        else if (t == 1) { s1 += vs; d1 += vd; }
        else if (t == 2) { s2 += vs; d2 += vd; }
        else { s3 += vs; d3 += vd; }
    }
    s0 = wredsum(s0); s1 = wredsum(s1); s2 = wredsum(s2); s3 = wredsum(s3);
    d0 = wredsum(d0); d1 = wredsum(d1); d2 = wredsum(d2); d3 = wredsum(d3);
    if (lane == 0) {
        as4[warp * 4 + 0] = s0; as4[warp * 4 + 1] = s1; as4[warp * 4 + 2] = s2; as4[warp * 4 + 3] = s3;
        ad4[warp * 4 + 0] = d0; ad4[warp * 4 + 1] = d1; ad4[warp * 4 + 2] = d2; ad4[warp * 4 + 3] = d3;
    }
}

// ---------------- fused task aggregation + log_softmax -> d_out ----------------
__global__ void gat_task(const float* __restrict__ Ht, const float* __restrict__ asv,
                         const float* __restrict__ adv, const int* __restrict__ rowp,
                         const int* __restrict__ col, const float* __restrict__ bias,
                         float* __restrict__ out, int n) {
    int warp = (blockIdx.x * blockDim.x + threadIdx.x) >> 5;
    int lane = threadIdx.x & 31;
    if (warp >= n) return;
    int node = warp;
    float asn = 0.f, adn = 0.f;
    if (lane < 4) { asn = asv[node * 4 + lane]; adn = adv[node * 4 + lane]; }
    float adt[4], mt[4];
#pragma unroll
    for (int t = 0; t < 4; t++) {
        adt[t] = __shfl_sync(FULLM, adn, t);
        mt[t] = lrelu(__shfl_sync(FULLM, asn, t) + adt[t]);
    }
    int beg = rowp[node], end = rowp[node + 1];
    for (int i = beg + lane; i < end; i += 32) {
        int src = col[i];
        const float* ap = asv + src * 4;
#pragma unroll
        for (int t = 0; t < 4; t++) mt[t] = fmaxf(mt[t], lrelu(ap[t] + adt[t]));
    }
#pragma unroll
    for (int t = 0; t < 4; t++) mt[t] = wredmax(mt[t]);
    float m_mine = mt[0];
    if (lane == 1) m_mine = mt[1];
    if (lane == 2) m_mine = mt[2];
    if (lane == 3) m_mine = mt[3];

    float acc[7];
    int tk[7];
#pragma unroll
    for (int k = 0; k < 7; k++) {
        acc[k] = 0.f;
        int c = lane + 32 * k;
        tk[k] = (c >= 12) + (c >= 42) + (c >= 102);
    }
    float ssum = 0.f;
    {   // self loop
        float w = 0.f;
        if (lane < 4) { w = expf(lrelu(asn + adn) - m_mine); ssum += w; }
        const float* hs = Ht + (size_t)node * 224;
#pragma unroll
        for (int k = 0; k < 7; k++) acc[k] += __shfl_sync(FULLM, w, tk[k]) * hs[lane + 32 * k];
    }
    for (int i = beg; i < end; ++i) {
        int src = col[i];
        float w = 0.f;
        if (lane < 4) { w = expf(lrelu(asv[src * 4 + lane] + adn) - m_mine); ssum += w; }
        const float* hs = Ht + (size_t)src * 224;
#pragma unroll
        for (int k = 0; k < 7; k++) acc[k] += __shfl_sync(FULLM, w, tk[k]) * hs[lane + 32 * k];
    }
    float v[7];
#pragma unroll
    for (int k = 0; k < 7; k++) {
        float denom = __shfl_sync(FULLM, ssum, tk[k]) + 1e-16f;
        v[k] = acc[k] / denom + bias[lane + 32 * k];
    }
    const int Cc[4]  = {12, 30, 60, 120};
    const int Off[4] = {0, 12, 42, 102};
    size_t bases[4];
    bases[0] = 0; bases[1] = (size_t)n * 12; bases[2] = (size_t)n * 42; bases[3] = (size_t)n * 102;
#pragma unroll
    for (int t = 0; t < 4; t++) {
        float mx = -1e30f;
#pragma unroll
        for (int k = 0; k < 7; k++) { int c = lane + 32 * k; if (tk[k] == t && c < 222) mx = fmaxf(mx, v[k]); }
        mx = wredmax(mx);
        float se = 0.f;
#pragma unroll
        for (int k = 0; k < 7; k++) { int c = lane + 32 * k; if (tk[k] == t && c < 222) se += expf(v[k] - mx); }
        se = wredsum(se);
        float lse = mx + logf(se);
#pragma unroll
        for (int k = 0; k < 7; k++) {
            int c = lane + 32 * k;
            if (tk[k] == t && c < 222)
                out[bases[t] + (size_t)node * Cc[t] + (c - Off[t])] = v[k] - lse;
        }
    }
}

// ---------------- launch ----------------
extern "C" void kernel_launch(void* const* d_in, const int* in_sizes, int n_in,
                              void* d_out, int out_size) {
    const float* x   = (const float*)d_in[0];
    const int*   ei  = (const int*)d_in[1];
    const float* W1  = (const float*)d_in[2];
    const float* a1s = (const float*)d_in[3];
    const float* a1d = (const float*)d_in[4];
    const float* b1  = (const float*)d_in[5];
    const float* W2  = (const float*)d_in[6];
    const float* a2s = (const float*)d_in[7];
    const float* a2d = (const float*)d_in[8];
    const float* b2  = (const float*)d_in[9];
    const float* W_TL = (const float*)d_in[10], *as_TL = (const float*)d_in[11], *ad_TL = (const float*)d_in[12], *b_TL = (const float*)d_in[13];
    const float* W_YL = (const float*)d_in[14], *as_YL = (const float*)d_in[15], *ad_YL = (const float*)d_in[16], *b_YL = (const float*)d_in[17];
    const float* W_TS = (const float*)d_in[18], *as_TS = (const float*)d_in[19], *ad_TS = (const float*)d_in[20], *b_TS = (const float*)d_in[21];
    const float* W_TZ = (const float*)d_in[22], *as_TZ = (const float*)d_in[23], *ad_TZ = (const float*)d_in[24], *b_TZ = (const float*)d_in[25];

    int N = in_sizes[0] / 128;
    int E = in_sizes[1] / 2;

    float *bufA, *bufB, *asv, *adv, *as4, *ad4, *Wcat, *acs, *acd, *bc;
    int *deg, *rowp, *cursor, *col;
    cudaGetSymbolAddress((void**)&bufA, g_bufA);
    cudaGetSymbolAddress((void**)&bufB, g_bufB);
    cudaGetSymbolAddress((void**)&asv, g_as);
    cudaGetSymbolAddress((void**)&adv, g_ad);
    cudaGetSymbolAddress((void**)&as4, g_as4);
    cudaGetSymbolAddress((void**)&ad4, g_ad4);
    cudaGetSymbolAddress((void**)&Wcat, g_Wcat);
    cudaGetSymbolAddress((void**)&acs, g_acs);
    cudaGetSymbolAddress((void**)&acd, g_acd);
    cudaGetSymbolAddress((void**)&bc, g_bc);
    cudaGetSymbolAddress((void**)&deg, g_deg);
    cudaGetSymbolAddress((void**)&rowp, g_rowp);
    cudaGetSymbolAddress((void**)&cursor, g_cursor);
    cudaGetSymbolAddress((void**)&col, g_col);

    int warpsGrid = (N + 7) / 8;          // one warp per node, 8 warps per block
    int eGrid = (E + 255) / 256;

    // CSR build (by dst)
    zero_int<<<(N + 255) / 256, 256>>>(deg, N);
    count_deg<<<eGrid, 256>>>(ei, E, deg);
    scan_block<<<1, 1024>>>(deg, rowp, N);
    copy_int<<<(N + 255) / 256, 256>>>(rowp, cursor, N);
    fill_col<<<eGrid, 256>>>(ei, E, cursor, col);

    // conv1
    dim3 g1(2, (N + 127) / 128);
    sgemm128<<<g1, 256>>>(x, W1, bufA, N, 256, 128);
    alpha_conv<<<warpsGrid, 256>>>(bufA, a1s, a1d, asv, adv, N);
    gat_agg_conv<<<warpsGrid, 256>>>(bufA, asv, adv, rowp, col, b1, bufB, N, 1);

    // conv2
    sgemm128<<<g1, 256>>>(bufB, W2, bufA, N, 256, 256);
    alpha_conv<<<warpsGrid, 256>>>(bufA, a2s, a2d, asv, adv, N);
    gat_agg_conv<<<warpsGrid, 256>>>(bufA, asv, adv, rowp, col, b2, bufB, N, 0);

    // fused task heads
    pack_task<<<(256 * 224 + 255) / 256, 256>>>(W_TL, W_YL, W_TS, W_TZ,
                                                as_TL, as_YL, as_TS, as_TZ,
                                                ad_TL, ad_YL, ad_TS, ad_TZ,
                                                b_TL, b_YL, b_TS, b_TZ,
                                                Wcat, acs, acd, bc);
    dim3 g2(2, (N + 127) / 128);
    sgemm128<<<g2, 256>>>(bufB, Wcat, bufA, N, 224, 256);
    alpha_task<<<warpsGrid, 256>>>(bufA, acs, acd, as4, ad4, N);
    gat_task<<<warpsGrid, 256>>>(bufA, as4, ad4, rowp, col, bc, (float*)d_out, N);
}

// round 2
// speedup vs baseline: 1.0673x; 1.0673x over previous
#include <cuda_runtime.h>
#include <math.h>

#define NN 50000
#define EE 800000
#define FULLM 0xffffffffu

// ---------------- static scratch (no allocation allowed) ----------------
__device__ __align__(128) float g_bufA[NN * 256];   // gemm outputs / Ht (ld 224)
__device__ __align__(128) float g_bufB[NN * 256];   // aggregated outputs
__device__ float g_as[NN * 8];
__device__ float g_ad[NN * 8];
__device__ float g_as4[NN * 4];
__device__ float g_ad4[NN * 4];
__device__ __align__(128) float g_Wcat[256 * 224];
__device__ float g_acs[224];
__device__ float g_acd[224];
__device__ float g_bc[224];
__device__ int g_deg[NN];
__device__ int g_rowp[NN + 1];
__device__ int g_cursor[NN];
__device__ int g_col[EE];

// ---------------- helpers ----------------
__device__ __forceinline__ float wredsum(float v) {
#pragma unroll
    for (int o = 16; o > 0; o >>= 1) v += __shfl_xor_sync(FULLM, v, o);
    return v;
}
__device__ __forceinline__ float wredmax(float v) {
#pragma unroll
    for (int o = 16; o > 0; o >>= 1) v = fmaxf(v, __shfl_xor_sync(FULLM, v, o));
    return v;
}
__device__ __forceinline__ float lrelu(float e) { return e > 0.f ? e : 0.2f * e; }

__device__ __forceinline__ unsigned long long packf2(float a) {
    unsigned long long r;
    asm("mov.b64 %0, {%1, %1};" : "=l"(r) : "f"(a));
    return r;
}
__device__ __forceinline__ void ffma2(unsigned long long& acc, unsigned long long a,
                                      unsigned long long b) {
    asm("fma.rn.f32x2 %0, %1, %2, %0;" : "+l"(acc) : "l"(a), "l"(b));
}
__device__ __forceinline__ void unpackf2(unsigned long long v, float& lo, float& hi) {
    asm("mov.b64 {%0, %1}, %2;" : "=f"(lo), "=f"(hi) : "l"(v));
}

// ---------------- CSR build ----------------
__global__ void zero_int(int* p, int n) {
    int i = blockIdx.x * blockDim.x + threadIdx.x;
    if (i < n) p[i] = 0;
}
__global__ void count_deg(const int* __restrict__ ei, int E, int* deg) {
    int e = blockIdx.x * blockDim.x + threadIdx.x;
    if (e < E) atomicAdd(&deg[ei[E + e]], 1);
}
__global__ void scan_block(const int* __restrict__ deg, int* __restrict__ rowp,
                           int* __restrict__ cursor, int n) {
    __shared__ int sm[1024];
    int tid = threadIdx.x;
    int chunk = (n + 1023) >> 10;
    int start = tid * chunk;
    int s = 0;
    for (int i = 0; i < chunk; i++) { int id = start + i; if (id < n) s += deg[id]; }
    sm[tid] = s; __syncthreads();
    for (int o = 1; o < 1024; o <<= 1) {
        int t = (tid >= o) ? sm[tid - o] : 0;
        __syncthreads();
        sm[tid] += t;
        __syncthreads();
    }
    int run = sm[tid] - s;
    for (int i = 0; i < chunk; i++) {
        int id = start + i;
        if (id < n) { rowp[id] = run; cursor[id] = run; run += deg[id]; }
    }
    if (tid == 1023) rowp[n] = sm[1023];
}
__global__ void fill_col(const int* __restrict__ ei, int E, int* cursor, int* __restrict__ col) {
    int e = blockIdx.x * blockDim.x + threadIdx.x;
    if (e < E) {
        int s = ei[e];
        int d = ei[E + e];
        int p = atomicAdd(&cursor[d], 1);
        col[p] = s;
    }
}

// ---------------- SGEMM 128x128x16, 8x8 microtile, packed f32x2 FMA ----------------
// C[M,N] = A[M,K] * B[K,N], all row-major, lda=K, ldb=ldc=N (N multiple of 4, K multiple of 16)
__global__ __launch_bounds__(256, 2) void sgemm128(
    const float* __restrict__ A, const float* __restrict__ B, float* __restrict__ C,
    int M, int N, int K) {
    __shared__ float As[16][128];
    __shared__ float Bs[16][128];
    int tid = threadIdx.x;
    int tx = tid & 15, ty = tid >> 4;
    int rowBase = blockIdx.y * 128;
    int colBase = blockIdx.x * 128;
    unsigned long long acc2[8][4];
#pragma unroll
    for (int i = 0; i < 8; i++)
#pragma unroll
        for (int j = 0; j < 4; j++) acc2[i][j] = 0ull;

    for (int kt = 0; kt < K; kt += 16) {
#pragma unroll
        for (int i = 0; i < 2; i++) {
            int s = tid + i * 256;
            int r = s >> 2, c4 = (s & 3) << 2;
            float4 v = make_float4(0.f, 0.f, 0.f, 0.f);
            int gr = rowBase + r;
            if (gr < M) v = *(const float4*)(A + (size_t)gr * K + kt + c4);
            As[c4 + 0][r] = v.x; As[c4 + 1][r] = v.y; As[c4 + 2][r] = v.z; As[c4 + 3][r] = v.w;
        }
#pragma unroll
        for (int i = 0; i < 2; i++) {
            int s = tid + i * 256;
            int r = s >> 5, c4 = (s & 31) << 2;
            float4 v = make_float4(0.f, 0.f, 0.f, 0.f);
            int gc = colBase + c4;
            if (gc < N) v = *(const float4*)(B + (size_t)(kt + r) * N + gc);
            *(float4*)&Bs[r][c4] = v;
        }
        __syncthreads();
#pragma unroll
        for (int k = 0; k < 16; k++) {
            unsigned long long b2[4];
            const unsigned long long* bp = (const unsigned long long*)&Bs[k][tx * 8];
#pragma unroll
            for (int j = 0; j < 4; j++) b2[j] = bp[j];
            float a[8];
#pragma unroll
            for (int i = 0; i < 8; i++) a[i] = As[k][ty * 8 + i];
#pragma unroll
            for (int i = 0; i < 8; i++) {
                unsigned long long ap = packf2(a[i]);
#pragma unroll
                for (int j = 0; j < 4; j++) ffma2(acc2[i][j], ap, b2[j]);
            }
        }
        __syncthreads();
    }
#pragma unroll
    for (int i = 0; i < 8; i++) {
        int gr = rowBase + ty * 8 + i;
        if (gr >= M) continue;
#pragma unroll
        for (int j = 0; j < 2; j++) {
            int gc = colBase + tx * 8 + j * 4;
            if (gc < N) {
                float4 v;
                unpackf2(acc2[i][j * 2 + 0], v.x, v.y);
                unpackf2(acc2[i][j * 2 + 1], v.z, v.w);
                *(float4*)(C + (size_t)gr * N + gc) = v;
            }
        }
    }
}

// ---------------- per-node attention scalars (conv, 8 heads x 32 ch) ----------------
// lane owns 8 contiguous channels (lane*8 .. lane*8+7); head = lane>>2
__global__ void alpha_conv(const float* __restrict__ h, const float* __restrict__ a_s,
                           const float* __restrict__ a_d, float* __restrict__ as_out,
                           float* __restrict__ ad_out, int n) {
    int warp = (blockIdx.x * blockDim.x + threadIdx.x) >> 5;
    int lane = threadIdx.x & 31;
    if (warp >= n) return;
    const float* row = h + (size_t)warp * 256 + lane * 8;
    const float* sp = a_s + lane * 8;
    const float* dp = a_d + lane * 8;
    float4 v0 = *(const float4*)row, v1 = *(const float4*)(row + 4);
    float4 s0 = *(const float4*)sp, s1 = *(const float4*)(sp + 4);
    float4 d0 = *(const float4*)dp, d1 = *(const float4*)(dp + 4);
    float s = v0.x * s0.x + v0.y * s0.y + v0.z * s0.z + v0.w * s0.w
            + v1.x * s1.x + v1.y * s1.y + v1.z * s1.z + v1.w * s1.w;
    float d = v0.x * d0.x + v0.y * d0.y + v0.z * d0.z + v0.w * d0.w
            + v1.x * d1.x + v1.y * d1.y + v1.z * d1.z + v1.w * d1.w;
    s += __shfl_xor_sync(FULLM, s, 1); s += __shfl_xor_sync(FULLM, s, 2);
    d += __shfl_xor_sync(FULLM, d, 1); d += __shfl_xor_sync(FULLM, d, 2);
    if ((lane & 3) == 0) {
        as_out[warp * 8 + (lane >> 2)] = s;
        ad_out[warp * 8 + (lane >> 2)] = d;
    }
}

// ---------------- GAT aggregation (conv layers, 8 heads x 32 ch) ----------------
// lane owns 8 contiguous channels; per edge: 2x LDG.128 + 1 SHFL
__global__ void gat_agg_conv(const float* __restrict__ h, const float* __restrict__ asv,
                             const float* __restrict__ adv, const int* __restrict__ rowp,
                             const int* __restrict__ col, const float* __restrict__ bias,
                             float* __restrict__ out, int n, int do_elu) {
    int warp = (blockIdx.x * blockDim.x + threadIdx.x) >> 5;
    int lane = threadIdx.x & 31;
    if (warp >= n) return;
    int node = warp;
    int head = lane >> 2;
    float asn = 0.f, adn = 0.f;
    if (lane < 8) { asn = asv[node * 8 + lane]; adn = adv[node * 8 + lane]; }
    float adh[8], mh[8];
#pragma unroll
    for (int k = 0; k < 8; k++) {
        adh[k] = __shfl_sync(FULLM, adn, k);
        mh[k] = lrelu(__shfl_sync(FULLM, asn, k) + adh[k]);   // self-loop e initializes max
    }
    int beg = rowp[node], end = rowp[node + 1];
    // pass A: per-head max (lane-parallel over edges)
    for (int i = beg + lane; i < end; i += 32) {
        int src = col[i];
        const float* ap = asv + src * 8;
#pragma unroll
        for (int k = 0; k < 8; k++) mh[k] = fmaxf(mh[k], lrelu(ap[k] + adh[k]));
    }
#pragma unroll
    for (int k = 0; k < 8; k++) mh[k] = wredmax(mh[k]);
    float m_mine = mh[0];
#pragma unroll
    for (int k = 1; k < 8; k++) if (lane == k) m_mine = mh[k];
    // pass B: weighted accumulation
    float4 acc0 = make_float4(0.f, 0.f, 0.f, 0.f);
    float4 acc1 = make_float4(0.f, 0.f, 0.f, 0.f);
    float ssum = 0.f;
    {   // self loop
        float wl = 0.f;
        if (lane < 8) { wl = expf(lrelu(asn + adn) - m_mine); ssum += wl; }
        float we = __shfl_sync(FULLM, wl, head);
        const float* hs = h + (size_t)node * 256 + lane * 8;
        float4 v0 = *(const float4*)hs, v1 = *(const float4*)(hs + 4);
        acc0.x += we * v0.x; acc0.y += we * v0.y; acc0.z += we * v0.z; acc0.w += we * v0.w;
        acc1.x += we * v1.x; acc1.y += we * v1.y; acc1.z += we * v1.z; acc1.w += we * v1.w;
    }
    for (int i = beg; i < end; ++i) {
        int src = col[i];
        float wl = 0.f;
        if (lane < 8) { wl = expf(lrelu(asv[src * 8 + lane] + adn) - m_mine); ssum += wl; }
        float we = __shfl_sync(FULLM, wl, head);
        const float* hs = h + (size_t)src * 256 + lane * 8;
        float4 v0 = *(const float4*)hs, v1 = *(const float4*)(hs + 4);
        acc0.x += we * v0.x; acc0.y += we * v0.y; acc0.z += we * v0.z; acc0.w += we * v0.w;
        acc1.x += we * v1.x; acc1.y += we * v1.y; acc1.z += we * v1.z; acc1.w += we * v1.w;
    }
    float denom = __shfl_sync(FULLM, ssum, head) + 1e-16f;
    float inv = 1.f / denom;
    const float* bp = bias + lane * 8;
    float4 b0 = *(const float4*)bp, b1v = *(const float4*)(bp + 4);
    float o[8];
    o[0] = acc0.x * inv + b0.x; o[1] = acc0.y * inv + b0.y;
    o[2] = acc0.z * inv + b0.z; o[3] = acc0.w * inv + b0.w;
    o[4] = acc1.x * inv + b1v.x; o[5] = acc1.y * inv + b1v.y;
    o[6] = acc1.z * inv + b1v.z; o[7] = acc1.w * inv + b1v.w;
    if (do_elu) {
#pragma unroll
        for (int j = 0; j < 8; j++) o[j] = o[j] > 0.f ? o[j] : expm1f(o[j]);
    }
    float* op = out + (size_t)node * 256 + lane * 8;
    *(float4*)op = make_float4(o[0], o[1], o[2], o[3]);
    *(float4*)(op + 4) = make_float4(o[4], o[5], o[6], o[7]);
}

// ---------------- pack 4 task weight matrices / attn vectors / biases ----------------
__global__ void pack_task(const float* __restrict__ W0, const float* __restrict__ W1,
                          const float* __restrict__ W2, const float* __restrict__ W3,
                          const float* __restrict__ s0, const float* __restrict__ s1,
                          const float* __restrict__ s2, const float* __restrict__ s3,
                          const float* __restrict__ d0, const float* __restrict__ d1,
                          const float* __restrict__ d2, const float* __restrict__ d3,
                          const float* __restrict__ b0, const float* __restrict__ b1,
                          const float* __restrict__ b2, const float* __restrict__ b3,
                          float* __restrict__ Wcat, float* __restrict__ acs,
                          float* __restrict__ acd, float* __restrict__ bc) {
    int idx = blockIdx.x * blockDim.x + threadIdx.x;
    if (idx >= 256 * 224) return;
    int k = idx / 224, j = idx % 224;
    float v = 0.f;
    if (j < 12) v = W0[k * 12 + j];
    else if (j < 42) v = W1[k * 30 + (j - 12)];
    else if (j < 102) v = W2[k * 60 + (j - 42)];
    else if (j < 222) v = W3[k * 120 + (j - 102)];
    Wcat[idx] = v;
    if (k == 0) {
        float s = 0.f, d = 0.f, b = 0.f;
        if (j < 12)       { s = s0[j];        d = d0[j];        b = b0[j]; }
        else if (j < 42)  { s = s1[j - 12];   d = d1[j - 12];   b = b1[j - 12]; }
        else if (j < 102) { s = s2[j - 42];   d = d2[j - 42];   b = b2[j - 42]; }
        else if (j < 222) { s = s3[j - 102];  d = d3[j - 102];  b = b3[j - 102]; }
        acs[j] = s; acd[j] = d; bc[j] = b;
    }
}

// ---------------- per-node attention scalars (4 task heads) ----------------
__global__ void alpha_task(const float* __restrict__ Ht, const float* __restrict__ acs,
                           const float* __restrict__ acd, float* __restrict__ as4,
                           float* __restrict__ ad4, int n) {
    int warp = (blockIdx.x * blockDim.x + threadIdx.x) >> 5;
    int lane = threadIdx.x & 31;
    if (warp >= n) return;
    const float* row = Ht + (size_t)warp * 224;
    float s0 = 0, s1 = 0, s2 = 0, s3 = 0, d0 = 0, d1 = 0, d2 = 0, d3 = 0;
#pragma unroll
    for (int k = 0; k < 7; k++) {
        int c = lane + 32 * k;
        float hv = row[c];
        float vs = hv * acs[c], vd = hv * acd[c];   // pad channels have acs=acd=0
        int t = (c >= 12) + (c >= 42) + (c >= 102);
        if (t == 0) { s0 += vs; d0 += vd; }
        else if (t == 1) { s1 += vs; d1 += vd; }
        else if (t == 2) { s2 += vs; d2 += vd; }
        else { s3 += vs; d3 += vd; }
    }
    s0 = wredsum(s0); s1 = wredsum(s1); s2 = wredsum(s2); s3 = wredsum(s3);
    d0 = wredsum(d0); d1 = wredsum(d1); d2 = wredsum(d2); d3 = wredsum(d3);
    if (lane == 0) {
        as4[warp * 4 + 0] = s0; as4[warp * 4 + 1] = s1; as4[warp * 4 + 2] = s2; as4[warp * 4 + 3] = s3;
        ad4[warp * 4 + 0] = d0; ad4[warp * 4 + 1] = d1; ad4[warp * 4 + 2] = d2; ad4[warp * 4 + 3] = d3;
    }
}

// ---------------- fused task aggregation + log_softmax -> d_out ----------------
__global__ void gat_task(const float* __restrict__ Ht, const float* __restrict__ asv,
                         const float* __restrict__ adv, const int* __restrict__ rowp,
                         const int* __restrict__ col, const float* __restrict__ bias,
                         float* __restrict__ out, int n) {
    int warp = (blockIdx.x * blockDim.x + threadIdx.x) >> 5;
    int lane = threadIdx.x & 31;
    if (warp >= n) return;
    int node = warp;
    float asn = 0.f, adn = 0.f;
    if (lane < 4) { asn = asv[node * 4 + lane]; adn = adv[node * 4 + lane]; }
    float adt[4], mt[4];
#pragma unroll
    for (int t = 0; t < 4; t++) {
        adt[t] = __shfl_sync(FULLM, adn, t);
        mt[t] = lrelu(__shfl_sync(FULLM, asn, t) + adt[t]);
    }
    int beg = rowp[node], end = rowp[node + 1];
    for (int i = beg + lane; i < end; i += 32) {
        int src = col[i];
        const float* ap = asv + src * 4;
#pragma unroll
        for (int t = 0; t < 4; t++) mt[t] = fmaxf(mt[t], lrelu(ap[t] + adt[t]));
    }
#pragma unroll
    for (int t = 0; t < 4; t++) mt[t] = wredmax(mt[t]);
    float m_mine = mt[0];
    if (lane == 1) m_mine = mt[1];
    if (lane == 2) m_mine = mt[2];
    if (lane == 3) m_mine = mt[3];

    float acc[7];
    int tk[7];
#pragma unroll
    for (int k = 0; k < 7; k++) {
        acc[k] = 0.f;
        int c = lane + 32 * k;
        tk[k] = (c >= 12) + (c >= 42) + (c >= 102);
    }
    float ssum = 0.f;
    {   // self loop
        float w = 0.f;
        if (lane < 4) { w = expf(lrelu(asn + adn) - m_mine); ssum += w; }
        const float* hs = Ht + (size_t)node * 224;
#pragma unroll
        for (int k = 0; k < 7; k++) acc[k] += __shfl_sync(FULLM, w, tk[k]) * hs[lane + 32 * k];
    }
    for (int i = beg; i < end; ++i) {
        int src = col[i];
        float w = 0.f;
        if (lane < 4) { w = expf(lrelu(asv[src * 4 + lane] + adn) - m_mine); ssum += w; }
        const float* hs = Ht + (size_t)src * 224;
#pragma unroll
        for (int k = 0; k < 7; k++) acc[k] += __shfl_sync(FULLM, w, tk[k]) * hs[lane + 32 * k];
    }
    float v[7];
#pragma unroll
    for (int k = 0; k < 7; k++) {
        float denom = __shfl_sync(FULLM, ssum, tk[k]) + 1e-16f;
        v[k] = acc[k] / denom + bias[lane + 32 * k];
    }
    const int Cc[4]  = {12, 30, 60, 120};
    const int Off[4] = {0, 12, 42, 102};
    size_t bases[4];
    bases[0] = 0; bases[1] = (size_t)n * 12; bases[2] = (size_t)n * 42; bases[3] = (size_t)n * 102;
#pragma unroll
    for (int t = 0; t < 4; t++) {
        float mx = -1e30f;
#pragma unroll
        for (int k = 0; k < 7; k++) { int c = lane + 32 * k; if (tk[k] == t && c < 222) mx = fmaxf(mx, v[k]); }
        mx = wredmax(mx);
        float se = 0.f;
#pragma unroll
        for (int k = 0; k < 7; k++) { int c = lane + 32 * k; if (tk[k] == t && c < 222) se += expf(v[k] - mx); }
        se = wredsum(se);
        float lse = mx + logf(se);
#pragma unroll
        for (int k = 0; k < 7; k++) {
            int c = lane + 32 * k;
            if (tk[k] == t && c < 222)
                out[bases[t] + (size_t)node * Cc[t] + (c - Off[t])] = v[k] - lse;
        }
    }
}

// ---------------- launch ----------------
extern "C" void kernel_launch(void* const* d_in, const int* in_sizes, int n_in,
                              void* d_out, int out_size) {
    const float* x   = (const float*)d_in[0];
    const int*   ei  = (const int*)d_in[1];
    const float* W1  = (const float*)d_in[2];
    const float* a1s = (const float*)d_in[3];
    const float* a1d = (const float*)d_in[4];
    const float* b1  = (const float*)d_in[5];
    const float* W2  = (const float*)d_in[6];
    const float* a2s = (const float*)d_in[7];
    const float* a2d = (const float*)d_in[8];
    const float* b2  = (const float*)d_in[9];
    const float* W_TL = (const float*)d_in[10], *as_TL = (const float*)d_in[11], *ad_TL = (const float*)d_in[12], *b_TL = (const float*)d_in[13];
    const float* W_YL = (const float*)d_in[14], *as_YL = (const float*)d_in[15], *ad_YL = (const float*)d_in[16], *b_YL = (const float*)d_in[17];
    const float* W_TS = (const float*)d_in[18], *as_TS = (const float*)d_in[19], *ad_TS = (const float*)d_in[20], *b_TS = (const float*)d_in[21];
    const float* W_TZ = (const float*)d_in[22], *as_TZ = (const float*)d_in[23], *ad_TZ = (const float*)d_in[24], *b_TZ = (const float*)d_in[25];

    int N = in_sizes[0] / 128;
    int E = in_sizes[1] / 2;

    float *bufA, *bufB, *asv, *adv, *as4, *ad4, *Wcat, *acs, *acd, *bc;
    int *deg, *rowp, *cursor, *col;
    cudaGetSymbolAddress((void**)&bufA, g_bufA);
    cudaGetSymbolAddress((void**)&bufB, g_bufB);
    cudaGetSymbolAddress((void**)&asv, g_as);
    cudaGetSymbolAddress((void**)&adv, g_ad);
    cudaGetSymbolAddress((void**)&as4, g_as4);
    cudaGetSymbolAddress((void**)&ad4, g_ad4);
    cudaGetSymbolAddress((void**)&Wcat, g_Wcat);
    cudaGetSymbolAddress((void**)&acs, g_acs);
    cudaGetSymbolAddress((void**)&acd, g_acd);
    cudaGetSymbolAddress((void**)&bc, g_bc);
    cudaGetSymbolAddress((void**)&deg, g_deg);
    cudaGetSymbolAddress((void**)&rowp, g_rowp);
    cudaGetSymbolAddress((void**)&cursor, g_cursor);
    cudaGetSymbolAddress((void**)&col, g_col);

    int warpsGrid = (N + 7) / 8;          // one warp per node, 8 warps per block
    int eGrid = (E + 255) / 256;

    // CSR build (by dst)
    zero_int<<<(N + 255) / 256, 256>>>(deg, N);
    count_deg<<<eGrid, 256>>>(ei, E, deg);
    scan_block<<<1, 1024>>>(deg, rowp, cursor, N);
    fill_col<<<eGrid, 256>>>(ei, E, cursor, col);

    // conv1
    dim3 g1(2, (N + 127) / 128);
    sgemm128<<<g1, 256>>>(x, W1, bufA, N, 256, 128);
    alpha_conv<<<warpsGrid, 256>>>(bufA, a1s, a1d, asv, adv, N);
    gat_agg_conv<<<warpsGrid, 256>>>(bufA, asv, adv, rowp, col, b1, bufB, N, 1);

    // conv2
    sgemm128<<<g1, 256>>>(bufB, W2, bufA, N, 256, 256);
    alpha_conv<<<warpsGrid, 256>>>(bufA, a2s, a2d, asv, adv, N);
    gat_agg_conv<<<warpsGrid, 256>>>(bufA, asv, adv, rowp, col, b2, bufB, N, 0);

    // fused task heads
    pack_task<<<(256 * 224 + 255) / 256, 256>>>(W_TL, W_YL, W_TS, W_TZ,
                                                as_TL, as_YL, as_TS, as_TZ,
                                                ad_TL, ad_YL, ad_TS, ad_TZ,
                                                b_TL, b_YL, b_TS, b_TZ,
                                                Wcat, acs, acd, bc);
    dim3 g2(2, (N + 127) / 128);
    sgemm128<<<g2, 256>>>(bufB, Wcat, bufA, N, 224, 256);
    alpha_task<<<warpsGrid, 256>>>(bufA, acs, acd, as4, ad4, N);
    gat_task<<<warpsGrid, 256>>>(bufA, as4, ad4, rowp, col, bc, (float*)d_out, N);
}

// round 3
// speedup vs baseline: 1.1631x; 1.0897x over previous
#include <cuda_runtime.h>
#include <math.h>

#define NN 50000
#define EE 800000
#define FULLM 0xffffffffu

// ---------------- static scratch (no allocation allowed) ----------------
__device__ __align__(128) float g_bufA[NN * 256];   // gemm outputs / Ht (ld 224)
__device__ __align__(128) float g_bufB[NN * 256];   // aggregated outputs
__device__ float g_as[NN * 8];
__device__ float g_ad[NN * 8];
__device__ float g_as4[NN * 4];
__device__ float g_ad4[NN * 4];
__device__ __align__(128) float g_Wcat[256 * 224];
__device__ float g_acs[224];
__device__ float g_acd[224];
__device__ float g_bc[224];
__device__ int g_deg[NN];
__device__ int g_rowp[NN + 1];
__device__ int g_cursor[NN];
__device__ int g_col[EE];

// ---------------- helpers ----------------
__device__ __forceinline__ float wredsum(float v) {
#pragma unroll
    for (int o = 16; o > 0; o >>= 1) v += __shfl_xor_sync(FULLM, v, o);
    return v;
}
__device__ __forceinline__ float wredmax(float v) {
#pragma unroll
    for (int o = 16; o > 0; o >>= 1) v = fmaxf(v, __shfl_xor_sync(FULLM, v, o));
    return v;
}
__device__ __forceinline__ float lrelu(float e) { return e > 0.f ? e : 0.2f * e; }

__device__ __forceinline__ unsigned long long packf2(float a) {
    unsigned long long r;
    asm("mov.b64 %0, {%1, %1};" : "=l"(r) : "f"(a));
    return r;
}
__device__ __forceinline__ void ffma2(unsigned long long& acc, unsigned long long a,
                                      unsigned long long b) {
    asm("fma.rn.f32x2 %0, %1, %2, %0;" : "+l"(acc) : "l"(a), "l"(b));
}
__device__ __forceinline__ void unpackf2(unsigned long long v, float& lo, float& hi) {
    asm("mov.b64 {%0, %1}, %2;" : "=f"(lo), "=f"(hi) : "l"(v));
}

// ---------------- CSR build ----------------
__global__ void zero_int(int* p, int n) {
    int i = blockIdx.x * blockDim.x + threadIdx.x;
    if (i < n) p[i] = 0;
}
__global__ void count_deg(const int* __restrict__ ei, int E, int* deg) {
    int e = blockIdx.x * blockDim.x + threadIdx.x;
    if (e < E) atomicAdd(&deg[ei[E + e]], 1);
}
__global__ void scan_block(const int* __restrict__ deg, int* __restrict__ rowp,
                           int* __restrict__ cursor, int n) {
    __shared__ int sm[1024];
    int tid = threadIdx.x;
    int chunk = (n + 1023) >> 10;
    int start = tid * chunk;
    int s = 0;
    for (int i = 0; i < chunk; i++) { int id = start + i; if (id < n) s += deg[id]; }
    sm[tid] = s; __syncthreads();
    for (int o = 1; o < 1024; o <<= 1) {
        int t = (tid >= o) ? sm[tid - o] : 0;
        __syncthreads();
        sm[tid] += t;
        __syncthreads();
    }
    int run = sm[tid] - s;
    for (int i = 0; i < chunk; i++) {
        int id = start + i;
        if (id < n) { rowp[id] = run; cursor[id] = run; run += deg[id]; }
    }
    if (tid == 1023) rowp[n] = sm[1023];
}
__global__ void fill_col(const int* __restrict__ ei, int E, int* cursor, int* __restrict__ col) {
    int e = blockIdx.x * blockDim.x + threadIdx.x;
    if (e < E) {
        int s = ei[e];
        int d = ei[E + e];
        int p = atomicAdd(&cursor[d], 1);
        col[p] = s;
    }
}

// ---------------- SGEMM 128x128x16, 8x8 microtile, packed f32x2 FMA ----------------
// C[M,N] = A[M,K] * B[K,N], row-major. Optional fused alpha epilogue for conv layers
// (N==256, a_s/a_d are [256] head-major; writes as_out/ad_out [M,8]).
__global__ __launch_bounds__(256, 2) void sgemm128(
    const float* __restrict__ A, const float* __restrict__ B, float* __restrict__ C,
    int M, int N, int K,
    const float* __restrict__ a_s, const float* __restrict__ a_d,
    float* __restrict__ as_out, float* __restrict__ ad_out, int do_alpha) {
    __shared__ float As[16][128];
    __shared__ float Bs[16][128];
    int tid = threadIdx.x;
    int tx = tid & 15, ty = tid >> 4;
    int rowBase = blockIdx.y * 128;
    int colBase = blockIdx.x * 128;
    unsigned long long acc2[8][4];
#pragma unroll
    for (int i = 0; i < 8; i++)
#pragma unroll
        for (int j = 0; j < 4; j++) acc2[i][j] = 0ull;

    for (int kt = 0; kt < K; kt += 16) {
#pragma unroll
        for (int i = 0; i < 2; i++) {
            int s = tid + i * 256;
            int r = s >> 2, c4 = (s & 3) << 2;
            float4 v = make_float4(0.f, 0.f, 0.f, 0.f);
            int gr = rowBase + r;
            if (gr < M) v = *(const float4*)(A + (size_t)gr * K + kt + c4);
            As[c4 + 0][r] = v.x; As[c4 + 1][r] = v.y; As[c4 + 2][r] = v.z; As[c4 + 3][r] = v.w;
        }
#pragma unroll
        for (int i = 0; i < 2; i++) {
            int s = tid + i * 256;
            int r = s >> 5, c4 = (s & 31) << 2;
            float4 v = make_float4(0.f, 0.f, 0.f, 0.f);
            int gc = colBase + c4;
            if (gc < N) v = *(const float4*)(B + (size_t)(kt + r) * N + gc);
            *(float4*)&Bs[r][c4] = v;
        }
        __syncthreads();
#pragma unroll
        for (int k = 0; k < 16; k++) {
            unsigned long long b2[4];
            const unsigned long long* bp = (const unsigned long long*)&Bs[k][tx * 8];
#pragma unroll
            for (int j = 0; j < 4; j++) b2[j] = bp[j];
            float a[8];
#pragma unroll
            for (int i = 0; i < 8; i++) a[i] = As[k][ty * 8 + i];
#pragma unroll
            for (int i = 0; i < 8; i++) {
                unsigned long long ap = packf2(a[i]);
#pragma unroll
                for (int j = 0; j < 4; j++) ffma2(acc2[i][j], ap, b2[j]);
            }
        }
        __syncthreads();
    }
#pragma unroll
    for (int i = 0; i < 8; i++) {
        int gr = rowBase + ty * 8 + i;
        if (gr >= M) continue;
#pragma unroll
        for (int j = 0; j < 2; j++) {
            int gc = colBase + tx * 8 + j * 4;
            if (gc < N) {
                float4 v;
                unpackf2(acc2[i][j * 2 + 0], v.x, v.y);
                unpackf2(acc2[i][j * 2 + 1], v.z, v.w);
                *(float4*)(C + (size_t)gr * N + gc) = v;
            }
        }
    }
    // fused alpha epilogue: each thread's 8 cols lie inside one head (32 ch);
    // quad (lanes xor 1,2) completes the head's 32-ch dot per row.
    if (do_alpha) {
        int lane = tid & 31;
        int hd = (colBase >> 5) + (tx >> 2);
        int gc = colBase + tx * 8;
        float4 s0 = *(const float4*)(a_s + gc), s1 = *(const float4*)(a_s + gc + 4);
        float4 d0 = *(const float4*)(a_d + gc), d1 = *(const float4*)(a_d + gc + 4);
#pragma unroll
        for (int i = 0; i < 8; i++) {
            float c0, c1, c2, c3, c4, c5, c6, c7;
            unpackf2(acc2[i][0], c0, c1);
            unpackf2(acc2[i][1], c2, c3);
            unpackf2(acc2[i][2], c4, c5);
            unpackf2(acc2[i][3], c6, c7);
            float s = c0 * s0.x + c1 * s0.y + c2 * s0.z + c3 * s0.w
                    + c4 * s1.x + c5 * s1.y + c6 * s1.z + c7 * s1.w;
            float d = c0 * d0.x + c1 * d0.y + c2 * d0.z + c3 * d0.w
                    + c4 * d1.x + c5 * d1.y + c6 * d1.z + c7 * d1.w;
            s += __shfl_xor_sync(FULLM, s, 1); s += __shfl_xor_sync(FULLM, s, 2);
            d += __shfl_xor_sync(FULLM, d, 1); d += __shfl_xor_sync(FULLM, d, 2);
            int gr = rowBase + ty * 8 + i;
            if ((lane & 3) == 0 && gr < M) {
                as_out[gr * 8 + hd] = s;
                ad_out[gr * 8 + hd] = d;
            }
        }
    }
}

// ---------------- GAT aggregation (conv layers): single pass, shift = self score ----
__global__ void gat_agg_conv(const float* __restrict__ h, const float* __restrict__ asv,
                             const float* __restrict__ adv, const int* __restrict__ rowp,
                             const int* __restrict__ col, const float* __restrict__ bias,
                             float* __restrict__ out, int n, int do_elu) {
    int warp = (blockIdx.x * blockDim.x + threadIdx.x) >> 5;
    int lane = threadIdx.x & 31;
    if (warp >= n) return;
    int node = warp;
    int head = lane >> 2;
    float asn = 0.f, adn = 0.f;
    if (lane < 8) { asn = asv[node * 8 + lane]; adn = adv[node * 8 + lane]; }
    float m = lrelu(asn + adn);               // shift (softmax invariant); w_self = 1
    float ssum = (lane < 8) ? 1.f : 0.f;
    const float* hs0 = h + (size_t)node * 256 + lane * 8;
    float4 acc0 = *(const float4*)hs0;
    float4 acc1 = *(const float4*)(hs0 + 4);
    int beg = rowp[node], end = rowp[node + 1];
    int i = beg;
    int srcn = 0; float ae_n = 0.f;
    float4 v0n = make_float4(0,0,0,0), v1n = make_float4(0,0,0,0);
    if (i < end) {
        srcn = col[i];
        if (lane < 8) ae_n = asv[srcn * 8 + lane];
        const float* hp = h + (size_t)srcn * 256 + lane * 8;
        v0n = *(const float4*)hp; v1n = *(const float4*)(hp + 4);
    }
    while (i < end) {
        float ae = ae_n; float4 v0 = v0n, v1 = v1n;
        int j = i + 1;
        if (j < end) {
            srcn = col[j];
            if (lane < 8) ae_n = asv[srcn * 8 + lane];
            const float* hp = h + (size_t)srcn * 256 + lane * 8;
            v0n = *(const float4*)hp; v1n = *(const float4*)(hp + 4);
        }
        float wl = 0.f;
        if (lane < 8) { wl = __expf(lrelu(ae + adn) - m); ssum += wl; }
        float we = __shfl_sync(FULLM, wl, head);
        acc0.x = fmaf(we, v0.x, acc0.x); acc0.y = fmaf(we, v0.y, acc0.y);
        acc0.z = fmaf(we, v0.z, acc0.z); acc0.w = fmaf(we, v0.w, acc0.w);
        acc1.x = fmaf(we, v1.x, acc1.x); acc1.y = fmaf(we, v1.y, acc1.y);
        acc1.z = fmaf(we, v1.z, acc1.z); acc1.w = fmaf(we, v1.w, acc1.w);
        i = j;
    }
    float denom = __shfl_sync(FULLM, ssum, head) + 1e-16f;
    float inv = 1.f / denom;
    const float* bp = bias + lane * 8;
    float4 b0 = *(const float4*)bp, b1v = *(const float4*)(bp + 4);
    float o[8];
    o[0] = acc0.x * inv + b0.x; o[1] = acc0.y * inv + b0.y;
    o[2] = acc0.z * inv + b0.z; o[3] = acc0.w * inv + b0.w;
    o[4] = acc1.x * inv + b1v.x; o[5] = acc1.y * inv + b1v.y;
    o[6] = acc1.z * inv + b1v.z; o[7] = acc1.w * inv + b1v.w;
    if (do_elu) {
#pragma unroll
        for (int j = 0; j < 8; j++) o[j] = o[j] > 0.f ? o[j] : expm1f(o[j]);
    }
    float* op = out + (size_t)node * 256 + lane * 8;
    *(float4*)op = make_float4(o[0], o[1], o[2], o[3]);
    *(float4*)(op + 4) = make_float4(o[4], o[5], o[6], o[7]);
}

// ---------------- pack 4 task weight matrices / attn vectors / biases ----------------
__global__ void pack_task(const float* __restrict__ W0, const float* __restrict__ W1,
                          const float* __restrict__ W2, const float* __restrict__ W3,
                          const float* __restrict__ s0, const float* __restrict__ s1,
                          const float* __restrict__ s2, const float* __restrict__ s3,
                          const float* __restrict__ d0, const float* __restrict__ d1,
                          const float* __restrict__ d2, const float* __restrict__ d3,
                          const float* __restrict__ b0, const float* __restrict__ b1,
                          const float* __restrict__ b2, const float* __restrict__ b3,
                          float* __restrict__ Wcat, float* __restrict__ acs,
                          float* __restrict__ acd, float* __restrict__ bc) {
    int idx = blockIdx.x * blockDim.x + threadIdx.x;
    if (idx >= 256 * 224) return;
    int k = idx / 224, j = idx % 224;
    float v = 0.f;
    if (j < 12) v = W0[k * 12 + j];
    else if (j < 42) v = W1[k * 30 + (j - 12)];
    else if (j < 102) v = W2[k * 60 + (j - 42)];
    else if (j < 222) v = W3[k * 120 + (j - 102)];
    Wcat[idx] = v;
    if (k == 0) {
        float s = 0.f, d = 0.f, b = 0.f;
        if (j < 12)       { s = s0[j];        d = d0[j];        b = b0[j]; }
        else if (j < 42)  { s = s1[j - 12];   d = d1[j - 12];   b = b1[j - 12]; }
        else if (j < 102) { s = s2[j - 42];   d = d2[j - 42];   b = b2[j - 42]; }
        else if (j < 222) { s = s3[j - 102];  d = d3[j - 102];  b = b3[j - 102]; }
        acs[j] = s; acd[j] = d; bc[j] = b;
    }
}

// ---------------- per-node attention scalars (4 task heads) ----------------
__global__ void alpha_task(const float* __restrict__ Ht, const float* __restrict__ acs,
                           const float* __restrict__ acd, float* __restrict__ as4,
                           float* __restrict__ ad4, int n) {
    int warp = (blockIdx.x * blockDim.x + threadIdx.x) >> 5;
    int lane = threadIdx.x & 31;
    if (warp >= n) return;
    const float* row = Ht + (size_t)warp * 224;
    float s0 = 0, s1 = 0, s2 = 0, s3 = 0, d0 = 0, d1 = 0, d2 = 0, d3 = 0;
#pragma unroll
    for (int k = 0; k < 7; k++) {
        int c = lane + 32 * k;
        float hv = row[c];
        float vs = hv * acs[c], vd = hv * acd[c];   // pad channels have acs=acd=0
        int t = (c >= 12) + (c >= 42) + (c >= 102);
        if (t == 0) { s0 += vs; d0 += vd; }
        else if (t == 1) { s1 += vs; d1 += vd; }
        else if (t == 2) { s2 += vs; d2 += vd; }
        else { s3 += vs; d3 += vd; }
    }
    s0 = wredsum(s0); s1 = wredsum(s1); s2 = wredsum(s2); s3 = wredsum(s3);
    d0 = wredsum(d0); d1 = wredsum(d1); d2 = wredsum(d2); d3 = wredsum(d3);
    if (lane == 0) {
        as4[warp * 4 + 0] = s0; as4[warp * 4 + 1] = s1; as4[warp * 4 + 2] = s2; as4[warp * 4 + 3] = s3;
        ad4[warp * 4 + 0] = d0; ad4[warp * 4 + 1] = d1; ad4[warp * 4 + 2] = d2; ad4[warp * 4 + 3] = d3;
    }
}

// ---------------- fused task aggregation + log_softmax -> d_out ----------------
__global__ void gat_task(const float* __restrict__ Ht, const float* __restrict__ asv,
                         const float* __restrict__ adv, const int* __restrict__ rowp,
                         const int* __restrict__ col, const float* __restrict__ bias,
                         float* __restrict__ out, int n) {
    int warp = (blockIdx.x * blockDim.x + threadIdx.x) >> 5;
    int lane = threadIdx.x & 31;
    if (warp >= n) return;
    int node = warp;
    float asn = 0.f, adn = 0.f;
    if (lane < 4) { asn = asv[node * 4 + lane]; adn = adv[node * 4 + lane]; }
    float m = lrelu(asn + adn);               // shift; self weight = 1
    float ssum = (lane < 4) ? 1.f : 0.f;
    float acc[7];
    int tk[7];
    const float* hself = Ht + (size_t)node * 224;
#pragma unroll
    for (int k = 0; k < 7; k++) {
        int c = lane + 32 * k;
        tk[k] = (c >= 12) + (c >= 42) + (c >= 102);
        acc[k] = hself[c];                    // self loop (weight 1)
    }
    int beg = rowp[node], end = rowp[node + 1];
    int i = beg;
    float ae_n = 0.f, vn[7];
    if (i < end) {
        int s = col[i];
        if (lane < 4) ae_n = asv[s * 4 + lane];
        const float* hp = Ht + (size_t)s * 224;
#pragma unroll
        for (int k = 0; k < 7; k++) vn[k] = hp[lane + 32 * k];
    }
    while (i < end) {
        float ae = ae_n;
        float v[7];
#pragma unroll
        for (int k = 0; k < 7; k++) v[k] = vn[k];
        int j = i + 1;
        if (j < end) {
            int s = col[j];
            if (lane < 4) ae_n = asv[s * 4 + lane];
            const float* hp = Ht + (size_t)s * 224;
#pragma unroll
            for (int k = 0; k < 7; k++) vn[k] = hp[lane + 32 * k];
        }
        float wl = 0.f;
        if (lane < 4) { wl = __expf(lrelu(ae + adn) - m); ssum += wl; }
#pragma unroll
        for (int k = 0; k < 7; k++) {
            float we = __shfl_sync(FULLM, wl, tk[k]);
            acc[k] = fmaf(we, v[k], acc[k]);
        }
        i = j;
    }
    float v[7];
#pragma unroll
    for (int k = 0; k < 7; k++) {
        float denom = __shfl_sync(FULLM, ssum, tk[k]) + 1e-16f;
        v[k] = acc[k] / denom + bias[lane + 32 * k];
    }
    const int Cc[4]  = {12, 30, 60, 120};
    const int Off[4] = {0, 12, 42, 102};
    size_t bases[4];
    bases[0] = 0; bases[1] = (size_t)n * 12; bases[2] = (size_t)n * 42; bases[3] = (size_t)n * 102;
#pragma unroll
    for (int t = 0; t < 4; t++) {
        float mx = -1e30f;
#pragma unroll
        for (int k = 0; k < 7; k++) { int c = lane + 32 * k; if (tk[k] == t && c < 222) mx = fmaxf(mx, v[k]); }
        mx = wredmax(mx);
        float se = 0.f;
#pragma unroll
        for (int k = 0; k < 7; k++) { int c = lane + 32 * k; if (tk[k] == t && c < 222) se += __expf(v[k] - mx); }
        se = wredsum(se);
        float lse = mx + __logf(se);
#pragma unroll
        for (int k = 0; k < 7; k++) {
            int c = lane + 32 * k;
            if (tk[k] == t && c < 222)
                out[bases[t] + (size_t)node * Cc[t] + (c - Off[t])] = v[k] - lse;
        }
    }
}

// ---------------- launch ----------------
extern "C" void kernel_launch(void* const* d_in, const int* in_sizes, int n_in,
                              void* d_out, int out_size) {
    const float* x   = (const float*)d_in[0];
    const int*   ei  = (const int*)d_in[1];
    const float* W1  = (const float*)d_in[2];
    const float* a1s = (const float*)d_in[3];
    const float* a1d = (const float*)d_in[4];
    const float* b1  = (const float*)d_in[5];
    const float* W2  = (const float*)d_in[6];
    const float* a2s = (const float*)d_in[7];
    const float* a2d = (const float*)d_in[8];
    const float* b2  = (const float*)d_in[9];
    const float* W_TL = (const float*)d_in[10], *as_TL = (const float*)d_in[11], *ad_TL = (const float*)d_in[12], *b_TL = (const float*)d_in[13];
    const float* W_YL = (const float*)d_in[14], *as_YL = (const float*)d_in[15], *ad_YL = (const float*)d_in[16], *b_YL = (const float*)d_in[17];
    const float* W_TS = (const float*)d_in[18], *as_TS = (const float*)d_in[19], *ad_TS = (const float*)d_in[20], *b_TS = (const float*)d_in[21];
    const float* W_TZ = (const float*)d_in[22], *as_TZ = (const float*)d_in[23], *ad_TZ = (const float*)d_in[24], *b_TZ = (const float*)d_in[25];

    int N = in_sizes[0] / 128;
    int E = in_sizes[1] / 2;

    float *bufA, *bufB, *asv, *adv, *as4, *ad4, *Wcat, *acs, *acd, *bc;
    int *deg, *rowp, *cursor, *col;
    cudaGetSymbolAddress((void**)&bufA, g_bufA);
    cudaGetSymbolAddress((void**)&bufB, g_bufB);
    cudaGetSymbolAddress((void**)&asv, g_as);
    cudaGetSymbolAddress((void**)&adv, g_ad);
    cudaGetSymbolAddress((void**)&as4, g_as4);
    cudaGetSymbolAddress((void**)&ad4, g_ad4);
    cudaGetSymbolAddress((void**)&Wcat, g_Wcat);
    cudaGetSymbolAddress((void**)&acs, g_acs);
    cudaGetSymbolAddress((void**)&acd, g_acd);
    cudaGetSymbolAddress((void**)&bc, g_bc);
    cudaGetSymbolAddress((void**)&deg, g_deg);
    cudaGetSymbolAddress((void**)&rowp, g_rowp);
    cudaGetSymbolAddress((void**)&cursor, g_cursor);
    cudaGetSymbolAddress((void**)&col, g_col);

    int warpsGrid = (N + 7) / 8;          // one warp per node, 8 warps per block
    int eGrid = (E + 255) / 256;
    dim3 g1(2, (N + 127) / 128);

    // launches 0-2: CSR prefix
    zero_int<<<(N + 255) / 256, 256>>>(deg, N);
    count_deg<<<eGrid, 256>>>(ei, E, deg);
    scan_block<<<1, 1024>>>(deg, rowp, cursor, N);
    // launch 3: conv1 GEMM (+fused alpha) — positioned here for ncu capture
    sgemm128<<<g1, 256>>>(x, W1, bufA, N, 256, 128, a1s, a1d, asv, adv, 1);
    // launch 4: finish CSR
    fill_col<<<eGrid, 256>>>(ei, E, cursor, col);
    // conv1 aggregation (+ELU)
    gat_agg_conv<<<warpsGrid, 256>>>(bufA, asv, adv, rowp, col, b1, bufB, N, 1);

    // conv2
    sgemm128<<<g1, 256>>>(bufB, W2, bufA, N, 256, 256, a2s, a2d, asv, adv, 1);
    gat_agg_conv<<<warpsGrid, 256>>>(bufA, asv, adv, rowp, col, b2, bufB, N, 0);

    // fused task heads
    pack_task<<<(256 * 224 + 255) / 256, 256>>>(W_TL, W_YL, W_TS, W_TZ,
                                                as_TL, as_YL, as_TS, as_TZ,
                                                ad_TL, ad_YL, ad_TS, ad_TZ,
                                                b_TL, b_YL, b_TS, b_TZ,
                                                Wcat, acs, acd, bc);
    sgemm128<<<g1, 256>>>(bufB, Wcat, bufA, N, 224, 256, (const float*)0, (const float*)0,
                          (float*)0, (float*)0, 0);
    alpha_task<<<warpsGrid, 256>>>(bufA, acs, acd, as4, ad4, N);
    gat_task<<<warpsGrid, 256>>>(bufA, as4, ad4, rowp, col, bc, (float*)d_out, N);
}

// round 4
// speedup vs baseline: 1.1858x; 1.0195x over previous
#include <cuda_runtime.h>
#include <math.h>

#define NN 50000
#define EE 800000
#define FULLM 0xffffffffu

// ---------------- static scratch (no allocation allowed) ----------------
__device__ __align__(128) float g_bufA[NN * 256];   // gemm outputs / Ht (ld 224)
__device__ __align__(128) float g_bufB[NN * 256];   // aggregated outputs
__device__ float g_as[NN * 8];
__device__ float g_ad[NN * 8];
__device__ float g_as4[NN * 4];
__device__ float g_ad4[NN * 4];
__device__ __align__(128) float g_Wcat[256 * 224];
__device__ float g_acs[224];
__device__ float g_acd[224];
__device__ float g_bc[224];
__device__ int g_deg[NN];
__device__ int g_rowp[NN + 1];
__device__ int g_cursor[NN];
__device__ int g_col[EE];

// ---------------- helpers ----------------
__device__ __forceinline__ float wredsum(float v) {
#pragma unroll
    for (int o = 16; o > 0; o >>= 1) v += __shfl_xor_sync(FULLM, v, o);
    return v;
}
__device__ __forceinline__ float wredmax(float v) {
#pragma unroll
    for (int o = 16; o > 0; o >>= 1) v = fmaxf(v, __shfl_xor_sync(FULLM, v, o));
    return v;
}
__device__ __forceinline__ float lrelu(float e) { return e > 0.f ? e : 0.2f * e; }

__device__ __forceinline__ unsigned long long packf2(float a) {
    unsigned long long r;
    asm("mov.b64 %0, {%1, %1};" : "=l"(r) : "f"(a));
    return r;
}
__device__ __forceinline__ void ffma2(unsigned long long& acc, unsigned long long a,
                                      unsigned long long b) {
    asm("fma.rn.f32x2 %0, %1, %2, %0;" : "+l"(acc) : "l"(a), "l"(b));
}
__device__ __forceinline__ void unpackf2(unsigned long long v, float& lo, float& hi) {
    asm("mov.b64 {%0, %1}, %2;" : "=f"(lo), "=f"(hi) : "l"(v));
}
__device__ __forceinline__ unsigned su32(const void* p) {
    unsigned r;
    asm("{ .reg .u64 t; cvta.to.shared.u64 t, %1; cvt.u32.u64 %0, t; }" : "=r"(r) : "l"(p));
    return r;
}
__device__ __forceinline__ void cpa16(unsigned dst, const float* src, int srcsize) {
    asm volatile("cp.async.ca.shared.global [%0], [%1], 16, %2;"
                 :: "r"(dst), "l"(src), "r"(srcsize));
}
#define CPA_COMMIT() asm volatile("cp.async.commit_group;" ::: "memory")
#define CPA_WAIT1()  asm volatile("cp.async.wait_group 1;" ::: "memory")

// ---------------- CSR build ----------------
__global__ void zero_int(int* p, int n) {
    int i = blockIdx.x * blockDim.x + threadIdx.x;
    if (i < n) p[i] = 0;
}
__global__ void count_deg(const int* __restrict__ ei, int E, int* deg) {
    int e = blockIdx.x * blockDim.x + threadIdx.x;
    if (e < E) atomicAdd(&deg[ei[E + e]], 1);
}
__global__ void scan_block(const int* __restrict__ deg, int* __restrict__ rowp,
                           int* __restrict__ cursor, int n) {
    __shared__ int sm[1024];
    int tid = threadIdx.x;
    int chunk = (n + 1023) >> 10;
    int start = tid * chunk;
    int s = 0;
    for (int i = 0; i < chunk; i++) { int id = start + i; if (id < n) s += deg[id]; }
    sm[tid] = s; __syncthreads();
    for (int o = 1; o < 1024; o <<= 1) {
        int t = (tid >= o) ? sm[tid - o] : 0;
        __syncthreads();
        sm[tid] += t;
        __syncthreads();
    }
    int run = sm[tid] - s;
    for (int i = 0; i < chunk; i++) {
        int id = start + i;
        if (id < n) { rowp[id] = run; cursor[id] = run; run += deg[id]; }
    }
    if (tid == 1023) rowp[n] = sm[1023];
}
__global__ void fill_col(const int* __restrict__ ei, int E, int* cursor, int* __restrict__ col) {
    int e = blockIdx.x * blockDim.x + threadIdx.x;
    if (e < E) {
        int s = ei[e];
        int d = ei[E + e];
        int p = atomicAdd(&cursor[d], 1);
        col[p] = s;
    }
}

// ---------------- SGEMM 128x128x16, 8x8 microtile, FFMA2 + cp.async double buffer ----
// C[M,N] = A[M,K] * B[K,N], row-major. K % 16 == 0. Optional fused alpha epilogue
// for conv layers (N==256, a_s/a_d are [256]; writes as_out/ad_out [M,8]).
__global__ __launch_bounds__(256, 2) void sgemm128(
    const float* __restrict__ A, const float* __restrict__ B, float* __restrict__ C,
    int M, int N, int K,
    const float* __restrict__ a_s, const float* __restrict__ a_d,
    float* __restrict__ as_out, float* __restrict__ ad_out, int do_alpha) {
    __shared__ float As[2][128 * 20];   // row-major, pad 20 floats/row
    __shared__ float Bs[2][16 * 128];
    int tid = threadIdx.x;
    int tx = tid & 15, ty = tid >> 4;
    int rowBase = blockIdx.y * 128;
    int colBase = blockIdx.x * 128;
    unsigned long long acc2[8][4];
#pragma unroll
    for (int i = 0; i < 8; i++)
#pragma unroll
        for (int j = 0; j < 4; j++) acc2[i][j] = 0ull;

    // tile copy: A tile 128x16 (512 quads), B tile 16x128 (512 quads); 2 quads each/thread
    auto issueTile = [&](int kt, int buf) {
#pragma unroll
        for (int i = 0; i < 2; i++) {
            int q = tid + i * 256;
            int r = q >> 2, c4 = (q & 3) << 2;
            int gr = rowBase + r;
            const float* src = (gr < M) ? (A + (size_t)gr * K + kt + c4) : A;
            cpa16(su32(&As[buf][r * 20 + c4]), src, (gr < M) ? 16 : 0);
        }
#pragma unroll
        for (int i = 0; i < 2; i++) {
            int q = tid + i * 256;
            int r = q >> 5, c4 = (q & 31) << 2;
            int gc = colBase + c4;
            const float* src = (gc < N) ? (B + (size_t)(kt + r) * N + gc) : B;
            cpa16(su32(&Bs[buf][r * 128 + c4]), src, (gc < N) ? 16 : 0);
        }
        CPA_COMMIT();
    };

    int T = K >> 4;
    issueTile(0, 0);
    for (int t = 0; t < T; t++) {
        if (t + 1 < T) issueTile((t + 1) << 4, (t + 1) & 1);
        else CPA_COMMIT();
        CPA_WAIT1();
        __syncthreads();
        const float* Ab = &As[t & 1][0];
        const float* Bb = &Bs[t & 1][0];
#pragma unroll
        for (int k4 = 0; k4 < 4; k4++) {
            float4 a4[8];
#pragma unroll
            for (int i = 0; i < 8; i++)
                a4[i] = *(const float4*)&Ab[(ty * 8 + i) * 20 + k4 * 4];
#pragma unroll
            for (int kk = 0; kk < 4; kk++) {
                int k = k4 * 4 + kk;
                const unsigned long long* bp =
                    (const unsigned long long*)&Bb[k * 128 + tx * 8];
                unsigned long long b0 = bp[0], b1 = bp[1], b2v = bp[2], b3v = bp[3];
#pragma unroll
                for (int i = 0; i < 8; i++) {
                    float av = (kk == 0) ? a4[i].x : (kk == 1) ? a4[i].y
                             : (kk == 2) ? a4[i].z : a4[i].w;
                    unsigned long long ap = packf2(av);
                    ffma2(acc2[i][0], ap, b0);
                    ffma2(acc2[i][1], ap, b1);
                    ffma2(acc2[i][2], ap, b2v);
                    ffma2(acc2[i][3], ap, b3v);
                }
            }
        }
        __syncthreads();
    }
#pragma unroll
    for (int i = 0; i < 8; i++) {
        int gr = rowBase + ty * 8 + i;
        if (gr >= M) continue;
#pragma unroll
        for (int j = 0; j < 2; j++) {
            int gc = colBase + tx * 8 + j * 4;
            if (gc < N) {
                float4 v;
                unpackf2(acc2[i][j * 2 + 0], v.x, v.y);
                unpackf2(acc2[i][j * 2 + 1], v.z, v.w);
                *(float4*)(C + (size_t)gr * N + gc) = v;
            }
        }
    }
    // fused alpha epilogue: thread's 8 cols lie within one head (32 ch);
    // quad (lanes xor 1,2) completes the head's 32-ch dot per row.
    if (do_alpha) {
        int lane = tid & 31;
        int hd = (colBase >> 5) + (tx >> 2);
        int gc = colBase + tx * 8;
        float4 s0 = *(const float4*)(a_s + gc), s1 = *(const float4*)(a_s + gc + 4);
        float4 d0 = *(const float4*)(a_d + gc), d1 = *(const float4*)(a_d + gc + 4);
#pragma unroll
        for (int i = 0; i < 8; i++) {
            float c0, c1, c2, c3, c4, c5, c6, c7;
            unpackf2(acc2[i][0], c0, c1);
            unpackf2(acc2[i][1], c2, c3);
            unpackf2(acc2[i][2], c4, c5);
            unpackf2(acc2[i][3], c6, c7);
            float s = c0 * s0.x + c1 * s0.y + c2 * s0.z + c3 * s0.w
                    + c4 * s1.x + c5 * s1.y + c6 * s1.z + c7 * s1.w;
            float d = c0 * d0.x + c1 * d0.y + c2 * d0.z + c3 * d0.w
                    + c4 * d1.x + c5 * d1.y + c6 * d1.z + c7 * d1.w;
            s += __shfl_xor_sync(FULLM, s, 1); s += __shfl_xor_sync(FULLM, s, 2);
            d += __shfl_xor_sync(FULLM, d, 1); d += __shfl_xor_sync(FULLM, d, 2);
            int gr = rowBase + ty * 8 + i;
            if ((lane & 3) == 0 && gr < M) {
                as_out[gr * 8 + hd] = s;
                ad_out[gr * 8 + hd] = d;
            }
        }
    }
}

// ---------------- GAT aggregation (conv): chunked, lane-parallel weights ----------------
__global__ void gat_agg_conv(const float* __restrict__ h, const float* __restrict__ asv,
                             const float* __restrict__ adv, const int* __restrict__ rowp,
                             const int* __restrict__ col, const float* __restrict__ bias,
                             float* __restrict__ out, int n, int do_elu) {
    __shared__ float ws[8][32][8];
    int wid = threadIdx.x >> 5, lane = threadIdx.x & 31;
    int node = blockIdx.x * 8 + wid;
    if (node >= n) return;
    int head = lane >> 2;
    float asn = 0.f, adn = 0.f;
    if (lane < 8) { asn = asv[node * 8 + lane]; adn = adv[node * 8 + lane]; }
    float m = lrelu(asn + adn);               // shift (softmax invariant); w_self = 1
    float adh[8], mh[8];
#pragma unroll
    for (int k = 0; k < 8; k++) {
        adh[k] = __shfl_sync(FULLM, adn, k);
        mh[k]  = __shfl_sync(FULLM, m, k);
    }
    const float* hs0 = h + (size_t)node * 256 + lane * 8;
    float4 acc0 = *(const float4*)hs0;
    float4 acc1 = *(const float4*)(hs0 + 4);
    float ssum = 1.f;                          // self weight per head
    int beg = rowp[node], end = rowp[node + 1];
    for (int base = beg; base < end; base += 32) {
        int i = base + lane;
        int src_l = 0;
        float4 wlo = make_float4(0.f, 0.f, 0.f, 0.f), whi = wlo;
        if (i < end) {
            src_l = col[i];
            const float4* ap = (const float4*)(asv + (size_t)src_l * 8);
            float4 a0 = ap[0], a1 = ap[1];
            wlo.x = __expf(lrelu(a0.x + adh[0]) - mh[0]);
            wlo.y = __expf(lrelu(a0.y + adh[1]) - mh[1]);
            wlo.z = __expf(lrelu(a0.z + adh[2]) - mh[2]);
            wlo.w = __expf(lrelu(a0.w + adh[3]) - mh[3]);
            whi.x = __expf(lrelu(a1.x + adh[4]) - mh[4]);
            whi.y = __expf(lrelu(a1.y + adh[5]) - mh[5]);
            whi.z = __expf(lrelu(a1.z + adh[6]) - mh[6]);
            whi.w = __expf(lrelu(a1.w + adh[7]) - mh[7]);
        }
        *(float4*)&ws[wid][lane][0] = wlo;
        *(float4*)&ws[wid][lane][4] = whi;
        __syncwarp();
        int cnt = min(32, end - base);
#pragma unroll 4
        for (int e = 0; e < cnt; e++) {
            float we = ws[wid][e][head];
            int se = __shfl_sync(FULLM, src_l, e);
            ssum += we;
            const float* hp = h + (size_t)se * 256 + lane * 8;
            float4 v0 = *(const float4*)hp, v1 = *(const float4*)(hp + 4);
            acc0.x = fmaf(we, v0.x, acc0.x); acc0.y = fmaf(we, v0.y, acc0.y);
            acc0.z = fmaf(we, v0.z, acc0.z); acc0.w = fmaf(we, v0.w, acc0.w);
            acc1.x = fmaf(we, v1.x, acc1.x); acc1.y = fmaf(we, v1.y, acc1.y);
            acc1.z = fmaf(we, v1.z, acc1.z); acc1.w = fmaf(we, v1.w, acc1.w);
        }
        __syncwarp();
    }
    float inv = 1.f / (ssum + 1e-16f);
    const float* bp = bias + lane * 8;
    float4 b0 = *(const float4*)bp, b1v = *(const float4*)(bp + 4);
    float o[8];
    o[0] = acc0.x * inv + b0.x;  o[1] = acc0.y * inv + b0.y;
    o[2] = acc0.z * inv + b0.z;  o[3] = acc0.w * inv + b0.w;
    o[4] = acc1.x * inv + b1v.x; o[5] = acc1.y * inv + b1v.y;
    o[6] = acc1.z * inv + b1v.z; o[7] = acc1.w * inv + b1v.w;
    if (do_elu) {
#pragma unroll
        for (int j = 0; j < 8; j++) o[j] = o[j] > 0.f ? o[j] : expm1f(o[j]);
    }
    float* op = out + (size_t)node * 256 + lane * 8;
    *(float4*)op = make_float4(o[0], o[1], o[2], o[3]);
    *(float4*)(op + 4) = make_float4(o[4], o[5], o[6], o[7]);
}

// ---------------- pack 4 task weight matrices / attn vectors / biases ----------------
__global__ void pack_task(const float* __restrict__ W0, const float* __restrict__ W1,
                          const float* __restrict__ W2, const float* __restrict__ W3,
                          const float* __restrict__ s0, const float* __restrict__ s1,
                          const float* __restrict__ s2, const float* __restrict__ s3,
                          const float* __restrict__ d0, const float* __restrict__ d1,
                          const float* __restrict__ d2, const float* __restrict__ d3,
                          const float* __restrict__ b0, const float* __restrict__ b1,
                          const float* __restrict__ b2, const float* __restrict__ b3,
                          float* __restrict__ Wcat, float* __restrict__ acs,
                          float* __restrict__ acd, float* __restrict__ bc) {
    int idx = blockIdx.x * blockDim.x + threadIdx.x;
    if (idx >= 256 * 224) return;
    int k = idx / 224, j = idx % 224;
    float v = 0.f;
    if (j < 12) v = W0[k * 12 + j];
    else if (j < 42) v = W1[k * 30 + (j - 12)];
    else if (j < 102) v = W2[k * 60 + (j - 42)];
    else if (j < 222) v = W3[k * 120 + (j - 102)];
    Wcat[idx] = v;
    if (k == 0) {
        float s = 0.f, d = 0.f, b = 0.f;
        if (j < 12)       { s = s0[j];        d = d0[j];        b = b0[j]; }
        else if (j < 42)  { s = s1[j - 12];   d = d1[j - 12];   b = b1[j - 12]; }
        else if (j < 102) { s = s2[j - 42];   d = d2[j - 42];   b = b2[j - 42]; }
        else if (j < 222) { s = s3[j - 102];  d = d3[j - 102];  b = b3[j - 102]; }
        acs[j] = s; acd[j] = d; bc[j] = b;
    }
}

// ---------------- per-node attention scalars (4 task heads) ----------------
__global__ void alpha_task(const float* __restrict__ Ht, const float* __restrict__ acs,
                           const float* __restrict__ acd, float* __restrict__ as4,
                           float* __restrict__ ad4, int n) {
    int warp = (blockIdx.x * blockDim.x + threadIdx.x) >> 5;
    int lane = threadIdx.x & 31;
    if (warp >= n) return;
    const float* row = Ht + (size_t)warp * 224;
    float s0 = 0, s1 = 0, s2 = 0, s3 = 0, d0 = 0, d1 = 0, d2 = 0, d3 = 0;
#pragma unroll
    for (int k = 0; k < 7; k++) {
        int c = lane + 32 * k;
        float hv = row[c];
        float vs = hv * acs[c], vd = hv * acd[c];   // pad channels have acs=acd=0
        int t = (c >= 12) + (c >= 42) + (c >= 102);
        if (t == 0) { s0 += vs; d0 += vd; }
        else if (t == 1) { s1 += vs; d1 += vd; }
        else if (t == 2) { s2 += vs; d2 += vd; }
        else { s3 += vs; d3 += vd; }
    }
    s0 = wredsum(s0); s1 = wredsum(s1); s2 = wredsum(s2); s3 = wredsum(s3);
    d0 = wredsum(d0); d1 = wredsum(d1); d2 = wredsum(d2); d3 = wredsum(d3);
    if (lane == 0) {
        as4[warp * 4 + 0] = s0; as4[warp * 4 + 1] = s1; as4[warp * 4 + 2] = s2; as4[warp * 4 + 3] = s3;
        ad4[warp * 4 + 0] = d0; ad4[warp * 4 + 1] = d1; ad4[warp * 4 + 2] = d2; ad4[warp * 4 + 3] = d3;
    }
}

// ---------------- fused task aggregation + log_softmax -> d_out ----------------
__global__ void gat_task(const float* __restrict__ Ht, const float* __restrict__ asv,
                         const float* __restrict__ adv, const int* __restrict__ rowp,
                         const int* __restrict__ col, const float* __restrict__ bias,
                         float* __restrict__ out, int n) {
    __shared__ float ws4[8][32][4];
    int wid = threadIdx.x >> 5, lane = threadIdx.x & 31;
    int node = blockIdx.x * 8 + wid;
    if (node >= n) return;
    float asn = 0.f, adn = 0.f;
    if (lane < 4) { asn = asv[node * 4 + lane]; adn = adv[node * 4 + lane]; }
    float m = lrelu(asn + adn);               // shift; self weight = 1
    float adt[4], mt[4];
#pragma unroll
    for (int t = 0; t < 4; t++) {
        adt[t] = __shfl_sync(FULLM, adn, t);
        mt[t]  = __shfl_sync(FULLM, m, t);
    }
    float acc[7];
    int tk[7];
    const float* hself = Ht + (size_t)node * 224;
#pragma unroll
    for (int k = 0; k < 7; k++) {
        int c = lane + 32 * k;
        tk[k] = (c >= 12) + (c >= 42) + (c >= 102);
        acc[k] = hself[c];                    // self loop (weight 1)
    }
    float su0 = 0.f, su1 = 0.f, su2 = 0.f, su3 = 0.f;
    int beg = rowp[node], end = rowp[node + 1];
    for (int base = beg; base < end; base += 32) {
        int i = base + lane;
        int src_l = 0;
        float4 w4 = make_float4(0.f, 0.f, 0.f, 0.f);
        if (i < end) {
            src_l = col[i];
            float4 aq = *(const float4*)(asv + (size_t)src_l * 4);
            w4.x = __expf(lrelu(aq.x + adt[0]) - mt[0]);
            w4.y = __expf(lrelu(aq.y + adt[1]) - mt[1]);
            w4.z = __expf(lrelu(aq.z + adt[2]) - mt[2]);
            w4.w = __expf(lrelu(aq.w + adt[3]) - mt[3]);
            su0 += w4.x; su1 += w4.y; su2 += w4.z; su3 += w4.w;
        }
        *(float4*)&ws4[wid][lane][0] = w4;
        __syncwarp();
        int cnt = min(32, end - base);
#pragma unroll 2
        for (int e = 0; e < cnt; e++) {
            int se = __shfl_sync(FULLM, src_l, e);
            const float* hp = Ht + (size_t)se * 224;
#pragma unroll
            for (int k = 0; k < 7; k++)
                acc[k] = fmaf(ws4[wid][e][tk[k]], hp[lane + 32 * k], acc[k]);
        }
        __syncwarp();
    }
    float t0 = wredsum(su0) + 1.f + 1e-16f;
    float t1 = wredsum(su1) + 1.f + 1e-16f;
    float t2 = wredsum(su2) + 1.f + 1e-16f;
    float t3 = wredsum(su3) + 1.f + 1e-16f;
    float v[7];
#pragma unroll
    for (int k = 0; k < 7; k++) {
        float dk = (tk[k] == 0) ? t0 : (tk[k] == 1) ? t1 : (tk[k] == 2) ? t2 : t3;
        v[k] = acc[k] / dk + bias[lane + 32 * k];
    }
    const int Cc[4]  = {12, 30, 60, 120};
    const int Off[4] = {0, 12, 42, 102};
    size_t bases[4];
    bases[0] = 0; bases[1] = (size_t)n * 12; bases[2] = (size_t)n * 42; bases[3] = (size_t)n * 102;
#pragma unroll
    for (int t = 0; t < 4; t++) {
        float mx = -1e30f;
#pragma unroll
        for (int k = 0; k < 7; k++) { int c = lane + 32 * k; if (tk[k] == t && c < 222) mx = fmaxf(mx, v[k]); }
        mx = wredmax(mx);
        float se = 0.f;
#pragma unroll
        for (int k = 0; k < 7; k++) { int c = lane + 32 * k; if (tk[k] == t && c < 222) se += __expf(v[k] - mx); }
        se = wredsum(se);
        float lse = mx + __logf(se);
#pragma unroll
        for (int k = 0; k < 7; k++) {
            int c = lane + 32 * k;
            if (tk[k] == t && c < 222)
                out[bases[t] + (size_t)node * Cc[t] + (c - Off[t])] = v[k] - lse;
        }
    }
}

// ---------------- launch ----------------
extern "C" void kernel_launch(void* const* d_in, const int* in_sizes, int n_in,
                              void* d_out, int out_size) {
    const float* x   = (const float*)d_in[0];
    const int*   ei  = (const int*)d_in[1];
    const float* W1  = (const float*)d_in[2];
    const float* a1s = (const float*)d_in[3];
    const float* a1d = (const float*)d_in[4];
    const float* b1  = (const float*)d_in[5];
    const float* W2  = (const float*)d_in[6];
    const float* a2s = (const float*)d_in[7];
    const float* a2d = (const float*)d_in[8];
    const float* b2  = (const float*)d_in[9];
    const float* W_TL = (const float*)d_in[10], *as_TL = (const float*)d_in[11], *ad_TL = (const float*)d_in[12], *b_TL = (const float*)d_in[13];
    const float* W_YL = (const float*)d_in[14], *as_YL = (const float*)d_in[15], *ad_YL = (const float*)d_in[16], *b_YL = (const float*)d_in[17];
    const float* W_TS = (const float*)d_in[18], *as_TS = (const float*)d_in[19], *ad_TS = (const float*)d_in[20], *b_TS = (const float*)d_in[21];
    const float* W_TZ = (const float*)d_in[22], *as_TZ = (const float*)d_in[23], *ad_TZ = (const float*)d_in[24], *b_TZ = (const float*)d_in[25];

    int N = in_sizes[0] / 128;
    int E = in_sizes[1] / 2;

    float *bufA, *bufB, *asv, *adv, *as4, *ad4, *Wcat, *acs, *acd, *bc;
    int *deg, *rowp, *cursor, *col;
    cudaGetSymbolAddress((void**)&bufA, g_bufA);
    cudaGetSymbolAddress((void**)&bufB, g_bufB);
    cudaGetSymbolAddress((void**)&asv, g_as);
    cudaGetSymbolAddress((void**)&adv, g_ad);
    cudaGetSymbolAddress((void**)&as4, g_as4);
    cudaGetSymbolAddress((void**)&ad4, g_ad4);
    cudaGetSymbolAddress((void**)&Wcat, g_Wcat);
    cudaGetSymbolAddress((void**)&acs, g_acs);
    cudaGetSymbolAddress((void**)&acd, g_acd);
    cudaGetSymbolAddress((void**)&bc, g_bc);
    cudaGetSymbolAddress((void**)&deg, g_deg);
    cudaGetSymbolAddress((void**)&rowp, g_rowp);
    cudaGetSymbolAddress((void**)&cursor, g_cursor);
    cudaGetSymbolAddress((void**)&col, g_col);

    int warpsGrid = (N + 7) / 8;          // one warp per node, 8 warps per block
    int eGrid = (E + 255) / 256;
    dim3 g1(2, (N + 127) / 128);

    // launches 0-2: CSR prefix
    zero_int<<<(N + 255) / 256, 256>>>(deg, N);
    count_deg<<<eGrid, 256>>>(ei, E, deg);
    scan_block<<<1, 1024>>>(deg, rowp, cursor, N);
    // launch 3: conv1 GEMM (+fused alpha) — positioned here for ncu capture
    sgemm128<<<g1, 256>>>(x, W1, bufA, N, 256, 128, a1s, a1d, asv, adv, 1);
    // launch 4: finish CSR
    fill_col<<<eGrid, 256>>>(ei, E, cursor, col);
    // conv1 aggregation (+ELU)
    gat_agg_conv<<<warpsGrid, 256>>>(bufA, asv, adv, rowp, col, b1, bufB, N, 1);

    // conv2
    sgemm128<<<g1, 256>>>(bufB, W2, bufA, N, 256, 256, a2s, a2d, asv, adv, 1);
    gat_agg_conv<<<warpsGrid, 256>>>(bufA, asv, adv, rowp, col, b2, bufB, N, 0);

    // fused task heads
    pack_task<<<(256 * 224 + 255) / 256, 256>>>(W_TL, W_YL, W_TS, W_TZ,
                                                as_TL, as_YL, as_TS, as_TZ,
                                                ad_TL, ad_YL, ad_TS, ad_TZ,
                                                b_TL, b_YL, b_TS, b_TZ,
                                                Wcat, acs, acd, bc);
    sgemm128<<<g1, 256>>>(bufB, Wcat, bufA, N, 224, 256, (const float*)0, (const float*)0,
                          (float*)0, (float*)0, 0);
    alpha_task<<<warpsGrid, 256>>>(bufA, acs, acd, as4, ad4, N);
    gat_task<<<warpsGrid, 256>>>(bufA, as4, ad4, rowp, col, bc, (float*)d_out, N);
}

// round 6
// speedup vs baseline: 1.5425x; 1.3009x over previous
#include <cuda_runtime.h>
#include <cuda_bf16.h>
#include <math.h>
#include <stdint.h>

#define NN 50000
#define NROWPAD 50048
#define EE 800000
#define FULLM 0xffffffffu

// ---------------- static scratch (no allocation allowed) ----------------
__device__ __align__(128) float g_bufA[NROWPAD * 256];      // fp32 GEMM outputs
__device__ __align__(128) __nv_bfloat16 g_xhi[NROWPAD * 128];
__device__ __align__(128) __nv_bfloat16 g_xlo[NROWPAD * 128];
__device__ __align__(128) __nv_bfloat16 g_hhi[NROWPAD * 256];
__device__ __align__(128) __nv_bfloat16 g_hlo[NROWPAD * 256];
__device__ __align__(128) __nv_bfloat16 g_B1hi[256 * 128];
__device__ __align__(128) __nv_bfloat16 g_B1lo[256 * 128];
__device__ __align__(128) __nv_bfloat16 g_B2hi[256 * 256];
__device__ __align__(128) __nv_bfloat16 g_B2lo[256 * 256];
__device__ __align__(128) __nv_bfloat16 g_Bthi[256 * 256];
__device__ __align__(128) __nv_bfloat16 g_Btlo[256 * 256];
__device__ float g_as[NN * 8];
__device__ float g_ad[NN * 8];
__device__ float g_as4[NN * 4];
__device__ float g_ad4[NN * 4];
__device__ float g_acs[224];
__device__ float g_acd[224];
__device__ float g_bc[224];
__device__ int g_deg[NN];
__device__ int g_rowp[NN + 1];
__device__ int g_cursor[NN];
__device__ int g_col[EE];

// ---------------- helpers ----------------
__device__ __forceinline__ float wredsum(float v) {
#pragma unroll
    for (int o = 16; o > 0; o >>= 1) v += __shfl_xor_sync(FULLM, v, o);
    return v;
}
__device__ __forceinline__ float wredmax(float v) {
#pragma unroll
    for (int o = 16; o > 0; o >>= 1) v = fmaxf(v, __shfl_xor_sync(FULLM, v, o));
    return v;
}
__device__ __forceinline__ float lrelu(float e) { return e > 0.f ? e : 0.2f * e; }
__device__ __forceinline__ unsigned su32(const void* p) {
    unsigned r;
    asm("{ .reg .u64 t; cvta.to.shared.u64 t, %1; cvt.u32.u64 %0, t; }" : "=r"(r) : "l"(p));
    return r;
}
__device__ __forceinline__ void splitbf(float v, __nv_bfloat16& h, __nv_bfloat16& l) {
    h = __float2bfloat16(v);
    l = __float2bfloat16(v - __bfloat162float(h));
}
__device__ __forceinline__ uint32_t pkbf(__nv_bfloat16 a, __nv_bfloat16 b) {
    __nv_bfloat162 t(a, b);
    return *(uint32_t*)&t;
}
__device__ __forceinline__ void cpa16b(uint32_t dst, const void* src) {
    asm volatile("cp.async.ca.shared.global [%0], [%1], 16;" :: "r"(dst), "l"(src));
}
#define CPA_COMMIT() asm volatile("cp.async.commit_group;" ::: "memory")
#define CPA_WAIT1()  asm volatile("cp.async.wait_group 1;" ::: "memory")

__device__ __forceinline__ void ldmx4(uint32_t* r, uint32_t addr) {
    asm volatile("ldmatrix.sync.aligned.m8n8.x4.shared.b16 {%0,%1,%2,%3}, [%4];"
                 : "=r"(r[0]), "=r"(r[1]), "=r"(r[2]), "=r"(r[3]) : "r"(addr));
}
__device__ __forceinline__ void mma16816(float* c, const uint32_t* a,
                                         uint32_t b0, uint32_t b1) {
    asm volatile(
        "mma.sync.aligned.m16n8k16.row.col.f32.bf16.bf16.f32 "
        "{%0,%1,%2,%3}, {%4,%5,%6,%7}, {%8,%9}, {%0,%1,%2,%3};"
        : "+f"(c[0]), "+f"(c[1]), "+f"(c[2]), "+f"(c[3])
        : "r"(a[0]), "r"(a[1]), "r"(a[2]), "r"(a[3]), "r"(b0), "r"(b1));
}

// ---------------- CSR build ----------------
__global__ void zero_int(int* p, int n) {
    int i = blockIdx.x * blockDim.x + threadIdx.x;
    if (i < n) p[i] = 0;
}
__global__ void count_deg(const int* __restrict__ ei, int E, int* deg) {
    int e = blockIdx.x * blockDim.x + threadIdx.x;
    if (e < E) atomicAdd(&deg[ei[E + e]], 1);
}
__global__ void scan_block(const int* __restrict__ deg, int* __restrict__ rowp,
                           int* __restrict__ cursor, int n) {
    __shared__ int sm[1024];
    int tid = threadIdx.x;
    int chunk = (n + 1023) >> 10;
    int start = tid * chunk;
    int s = 0;
    for (int i = 0; i < chunk; i++) { int id = start + i; if (id < n) s += deg[id]; }
    sm[tid] = s; __syncthreads();
    for (int o = 1; o < 1024; o <<= 1) {
        int t = (tid >= o) ? sm[tid - o] : 0;
        __syncthreads();
        sm[tid] += t;
        __syncthreads();
    }
    int run = sm[tid] - s;
    for (int i = 0; i < chunk; i++) {
        int id = start + i;
        if (id < n) { rowp[id] = run; cursor[id] = run; run += deg[id]; }
    }
    if (tid == 1023) rowp[n] = sm[1023];
}
__global__ void fill_col(const int* __restrict__ ei, int E, int* cursor, int* __restrict__ col) {
    int e = blockIdx.x * blockDim.x + threadIdx.x;
    if (e < E) {
        int s = ei[e];
        int d = ei[E + e];
        int p = atomicAdd(&cursor[d], 1);
        col[p] = s;
    }
}

// ---------------- input conversion fp32 -> bf16 hi/lo ----------------
__global__ void convert_x(const float* __restrict__ x, __nv_bfloat16* __restrict__ xhi,
                          __nv_bfloat16* __restrict__ xlo, int n) {
    int idx = blockIdx.x * blockDim.x + threadIdx.x;   // 4 floats each
    if (idx >= n * 32) return;
    int row = idx >> 5, c4 = (idx & 31) << 2;
    float4 v = *(const float4*)(x + (size_t)row * 128 + c4);
    __nv_bfloat16 h0, l0, h1, l1, h2, l2, h3, l3;
    splitbf(v.x, h0, l0); splitbf(v.y, h1, l1);
    splitbf(v.z, h2, l2); splitbf(v.w, h3, l3);
    uint2 hw = make_uint2(pkbf(h0, h1), pkbf(h2, h3));
    uint2 lw = make_uint2(pkbf(l0, l1), pkbf(l2, l3));
    *(uint2*)(xhi + (size_t)row * 128 + c4) = hw;
    *(uint2*)(xlo + (size_t)row * 128 + c4) = lw;
}

// ---------------- weight packs: W[K][256] -> B[n][K] bf16 hi/lo (transposed) ----------
__global__ void pack_w(const float* __restrict__ W, __nv_bfloat16* __restrict__ bh,
                       __nv_bfloat16* __restrict__ bl, int K) {
    int idx = blockIdx.x * blockDim.x + threadIdx.x;
    if (idx >= 256 * K) return;
    int n = idx / K, k = idx % K;
    float v = W[(size_t)k * 256 + n];
    __nv_bfloat16 h, l;
    splitbf(v, h, l);
    bh[idx] = h; bl[idx] = l;
}
__global__ void pack_wt(const float* __restrict__ W0, const float* __restrict__ W1,
                        const float* __restrict__ W2, const float* __restrict__ W3,
                        const float* __restrict__ s0, const float* __restrict__ s1,
                        const float* __restrict__ s2, const float* __restrict__ s3,
                        const float* __restrict__ d0, const float* __restrict__ d1,
                        const float* __restrict__ d2, const float* __restrict__ d3,
                        const float* __restrict__ b0, const float* __restrict__ b1,
                        const float* __restrict__ b2, const float* __restrict__ b3,
                        __nv_bfloat16* __restrict__ bh, __nv_bfloat16* __restrict__ bl,
                        float* __restrict__ acs, float* __restrict__ acd,
                        float* __restrict__ bc) {
    int idx = blockIdx.x * blockDim.x + threadIdx.x;
    if (idx >= 256 * 256) return;
    int n = idx >> 8, k = idx & 255;
    float v = 0.f;
    if (n < 12) v = W0[k * 12 + n];
    else if (n < 42) v = W1[k * 30 + (n - 12)];
    else if (n < 102) v = W2[k * 60 + (n - 42)];
    else if (n < 222) v = W3[k * 120 + (n - 102)];
    __nv_bfloat16 h, l;
    splitbf(v, h, l);
    bh[idx] = h; bl[idx] = l;
    if (k == 0 && n < 224) {
        float s = 0.f, d = 0.f, b = 0.f;
        if (n < 12)       { s = s0[n];        d = d0[n];        b = b0[n]; }
        else if (n < 42)  { s = s1[n - 12];   d = d1[n - 12];   b = b1[n - 12]; }
        else if (n < 102) { s = s2[n - 42];   d = d2[n - 42];   b = b2[n - 42]; }
        else if (n < 222) { s = s3[n - 102];  d = d3[n - 102];  b = b3[n - 102]; }
        acs[n] = s; acd[n] = d; bc[n] = b;
    }
}

// ---------------- bf16x3 GEMM via mma.sync: C[M,Nout] = A[M,K] * W ----------------
// A bf16 hi/lo [Mpad,K]; B bf16 hi/lo [256,K] (row n = output col, K-major).
// CTA tile 128x64, warp tile 32x32, K chunk 16, cp.async double buffer.
// smem per stage (bf16 elems, row stride 24): AH 0..3071, AL 3072..6143,
// BH 6144..7679, BL 7680..9215.
__global__ __launch_bounds__(256, 2) void gemm_mma(
    const __nv_bfloat16* __restrict__ Ah, const __nv_bfloat16* __restrict__ Al,
    const __nv_bfloat16* __restrict__ Bh, const __nv_bfloat16* __restrict__ Bl,
    float* __restrict__ C, int M, int K, int Nout,
    const float* __restrict__ a_s, const float* __restrict__ a_d,
    float* __restrict__ as_out, float* __restrict__ ad_out, int do_alpha) {
    __shared__ __nv_bfloat16 smem[2][9216];
    int tid = threadIdx.x, wid = tid >> 5, lane = tid & 31;
    int rowBase = blockIdx.y * 128, colBase = blockIdx.x * 64;
    int warpM = (wid & 3) * 32, warpN = (wid >> 2) * 32;
    int g = lane >> 2, tg = lane & 3;

    float c[2][4][4];
#pragma unroll
    for (int mt = 0; mt < 2; mt++)
#pragma unroll
        for (int nt = 0; nt < 4; nt++)
#pragma unroll
            for (int j = 0; j < 4; j++) c[mt][nt][j] = 0.f;

    int arow = tid >> 1, ahalf = (tid & 1) * 8;
    uint32_t adst = (uint32_t)(arow * 24 + ahalf);
    int brow = (tid & 127) >> 1;
    uint32_t bdst = (uint32_t)(brow * 24 + ahalf);

    auto issue = [&](int t, int buf) {
        int kc = t << 4;
        size_t aoff = (size_t)(rowBase + arow) * K + kc + ahalf;
        cpa16b(su32(&smem[buf][adst]), Ah + aoff);
        cpa16b(su32(&smem[buf][3072 + adst]), Al + aoff);
        if (tid < 128) {
            size_t boff = (size_t)(colBase + brow) * K + kc + ahalf;
            cpa16b(su32(&smem[buf][6144 + bdst]), Bh + boff);
            cpa16b(su32(&smem[buf][7680 + bdst]), Bl + boff);
        }
        CPA_COMMIT();
    };

    int T = K >> 4;
    issue(0, 0);
    for (int t = 0; t < T; t++) {
        if (t + 1 < T) issue(t + 1, (t + 1) & 1);
        else CPA_COMMIT();
        CPA_WAIT1();
        __syncthreads();
        uint32_t sb = su32(&smem[t & 1][0]);
        uint32_t aHi[2][4], aLo[2][4], bHi[2][4], bLo[2][4];
#pragma unroll
        for (int mt = 0; mt < 2; mt++) {
            uint32_t addr = sb + ((uint32_t)((warpM + mt * 16 + (lane & 15)) * 24
                                             + ((lane >> 4) & 1) * 8) << 1);
            ldmx4(aHi[mt], addr);
            ldmx4(aLo[mt], addr + 3072 * 2);
        }
#pragma unroll
        for (int nb = 0; nb < 2; nb++) {
            uint32_t addr = sb + ((uint32_t)(6144
                              + (warpN + nb * 16 + (lane & 7) + ((lane >> 4) & 1) * 8) * 24
                              + ((lane >> 3) & 1) * 8) << 1);
            ldmx4(bHi[nb], addr);
            ldmx4(bLo[nb], addr + 1536 * 2);
        }
#pragma unroll
        for (int mt = 0; mt < 2; mt++)
#pragma unroll
            for (int nt = 0; nt < 4; nt++) {
                int nb = nt >> 1, s = (nt & 1) * 2;
                mma16816(c[mt][nt], aHi[mt], bHi[nb][s], bHi[nb][s + 1]);
                mma16816(c[mt][nt], aHi[mt], bLo[nb][s], bLo[nb][s + 1]);
                mma16816(c[mt][nt], aLo[mt], bHi[nb][s], bHi[nb][s + 1]);
            }
        __syncthreads();
    }

    // store C (fp32)
#pragma unroll
    for (int mt = 0; mt < 2; mt++) {
        int r0 = rowBase + warpM + mt * 16 + g;
#pragma unroll
        for (int nt = 0; nt < 4; nt++) {
            int col = colBase + warpN + nt * 8 + tg * 2;
            if (col < Nout) {
                if (r0 < M)
                    *(float2*)(C + (size_t)r0 * Nout + col) = make_float2(c[mt][nt][0], c[mt][nt][1]);
                if (r0 + 8 < M)
                    *(float2*)(C + (size_t)(r0 + 8) * Nout + col) = make_float2(c[mt][nt][2], c[mt][nt][3]);
            }
        }
    }
    // fused per-head alpha (conv layers: head = 32 cols = warp's col range)
    if (do_alpha) {
        int head = (colBase + warpN) >> 5;
#pragma unroll
        for (int mt = 0; mt < 2; mt++) {
            float sl = 0.f, sh = 0.f, dl = 0.f, dh = 0.f;
#pragma unroll
            for (int nt = 0; nt < 4; nt++) {
                int col = colBase + warpN + nt * 8 + tg * 2;
                float s0 = a_s[col], s1 = a_s[col + 1];
                float d0 = a_d[col], d1 = a_d[col + 1];
                sl += c[mt][nt][0] * s0 + c[mt][nt][1] * s1;
                sh += c[mt][nt][2] * s0 + c[mt][nt][3] * s1;
                dl += c[mt][nt][0] * d0 + c[mt][nt][1] * d1;
                dh += c[mt][nt][2] * d0 + c[mt][nt][3] * d1;
            }
            sl += __shfl_xor_sync(FULLM, sl, 1); sl += __shfl_xor_sync(FULLM, sl, 2);
            sh += __shfl_xor_sync(FULLM, sh, 1); sh += __shfl_xor_sync(FULLM, sh, 2);
            dl += __shfl_xor_sync(FULLM, dl, 1); dl += __shfl_xor_sync(FULLM, dl, 2);
            dh += __shfl_xor_sync(FULLM, dh, 1); dh += __shfl_xor_sync(FULLM, dh, 2);
            if (tg == 0) {
                int r0 = rowBase + warpM + mt * 16 + g;
                if (r0 < M)     { as_out[r0 * 8 + head] = sl;       ad_out[r0 * 8 + head] = dl; }
                if (r0 + 8 < M) { as_out[(r0 + 8) * 8 + head] = sh; ad_out[(r0 + 8) * 8 + head] = dh; }
            }
        }
    }
}

// ---------------- GAT aggregation (conv): outputs bf16 hi/lo for next GEMM ----------
__global__ void gat_agg_conv(const float* __restrict__ h, const float* __restrict__ asv,
                             const float* __restrict__ adv, const int* __restrict__ rowp,
                             const int* __restrict__ col, const float* __restrict__ bias,
                             __nv_bfloat16* __restrict__ outHi,
                             __nv_bfloat16* __restrict__ outLo, int n, int do_elu) {
    __shared__ float ws[8][32][8];
    int wid = threadIdx.x >> 5, lane = threadIdx.x & 31;
    int node = blockIdx.x * 8 + wid;
    if (node >= n) return;
    int head = lane >> 2;
    float asn = 0.f, adn = 0.f;
    if (lane < 8) { asn = asv[node * 8 + lane]; adn = adv[node * 8 + lane]; }
    float m = lrelu(asn + adn);               // shift (softmax invariant); w_self = 1
    float adh[8], mh[8];
#pragma unroll
    for (int k = 0; k < 8; k++) {
        adh[k] = __shfl_sync(FULLM, adn, k);
        mh[k]  = __shfl_sync(FULLM, m, k);
    }
    const float* hs0 = h + (size_t)node * 256 + lane * 8;
    float4 acc0 = *(const float4*)hs0;
    float4 acc1 = *(const float4*)(hs0 + 4);
    float ssum = 1.f;                          // self weight per head
    int beg = rowp[node], end = rowp[node + 1];
    for (int base = beg; base < end; base += 32) {
        int i = base + lane;
        int src_l = 0;
        float4 wlo = make_float4(0.f, 0.f, 0.f, 0.f), whi = wlo;
        if (i < end) {
            src_l = col[i];
            const float4* ap = (const float4*)(asv + (size_t)src_l * 8);
            float4 a0 = ap[0], a1 = ap[1];
            wlo.x = __expf(lrelu(a0.x + adh[0]) - mh[0]);
            wlo.y = __expf(lrelu(a0.y + adh[1]) - mh[1]);
            wlo.z = __expf(lrelu(a0.z + adh[2]) - mh[2]);
            wlo.w = __expf(lrelu(a0.w + adh[3]) - mh[3]);
            whi.x = __expf(lrelu(a1.x + adh[4]) - mh[4]);
            whi.y = __expf(lrelu(a1.y + adh[5]) - mh[5]);
            whi.z = __expf(lrelu(a1.z + adh[6]) - mh[6]);
            whi.w = __expf(lrelu(a1.w + adh[7]) - mh[7]);
        }
        *(float4*)&ws[wid][lane][0] = wlo;
        *(float4*)&ws[wid][lane][4] = whi;
        __syncwarp();
        int cnt = min(32, end - base);
#pragma unroll 4
        for (int e = 0; e < cnt; e++) {
            float we = ws[wid][e][head];
            int se = __shfl_sync(FULLM, src_l, e);
            ssum += we;
            const float* hp = h + (size_t)se * 256 + lane * 8;
            float4 v0 = *(const float4*)hp, v1 = *(const float4*)(hp + 4);
            acc0.x = fmaf(we, v0.x, acc0.x); acc0.y = fmaf(we, v0.y, acc0.y);
            acc0.z = fmaf(we, v0.z, acc0.z); acc0.w = fmaf(we, v0.w, acc0.w);
            acc1.x = fmaf(we, v1.x, acc1.x); acc1.y = fmaf(we, v1.y, acc1.y);
            acc1.z = fmaf(we, v1.z, acc1.z); acc1.w = fmaf(we, v1.w, acc1.w);
        }
        __syncwarp();
    }
    float inv = 1.f / (ssum + 1e-16f);
    const float* bp = bias + lane * 8;
    float4 b0 = *(const float4*)bp, b1v = *(const float4*)(bp + 4);
    float o[8];
    o[0] = acc0.x * inv + b0.x;  o[1] = acc0.y * inv + b0.y;
    o[2] = acc0.z * inv + b0.z;  o[3] = acc0.w * inv + b0.w;
    o[4] = acc1.x * inv + b1v.x; o[5] = acc1.y * inv + b1v.y;
    o[6] = acc1.z * inv + b1v.z; o[7] = acc1.w * inv + b1v.w;
    if (do_elu) {
#pragma unroll
        for (int j = 0; j < 8; j++) o[j] = o[j] > 0.f ? o[j] : expm1f(o[j]);
    }
    uint32_t hw[4], lw[4];
#pragma unroll
    for (int j = 0; j < 4; j++) {
        __nv_bfloat16 ha, la, hb, lb;
        splitbf(o[2 * j], ha, la);
        splitbf(o[2 * j + 1], hb, lb);
        hw[j] = pkbf(ha, hb);
        lw[j] = pkbf(la, lb);
    }
    size_t off = (size_t)node * 256 + lane * 8;
    *(uint4*)(outHi + off) = make_uint4(hw[0], hw[1], hw[2], hw[3]);
    *(uint4*)(outLo + off) = make_uint4(lw[0], lw[1], lw[2], lw[3]);
}

// ---------------- per-node attention scalars (4 task heads) ----------------
__global__ void alpha_task(const float* __restrict__ Ht, const float* __restrict__ acs,
                           const float* __restrict__ acd, float* __restrict__ as4,
                           float* __restrict__ ad4, int n) {
    int warp = (blockIdx.x * blockDim.x + threadIdx.x) >> 5;
    int lane = threadIdx.x & 31;
    if (warp >= n) return;
    const float* row = Ht + (size_t)warp * 224;
    float s0 = 0, s1 = 0, s2 = 0, s3 = 0, d0 = 0, d1 = 0, d2 = 0, d3 = 0;
#pragma unroll
    for (int k = 0; k < 7; k++) {
        int c = lane + 32 * k;
        float hv = row[c];
        float vs = hv * acs[c], vd = hv * acd[c];
        int t = (c >= 12) + (c >= 42) + (c >= 102);
        if (t == 0) { s0 += vs; d0 += vd; }
        else if (t == 1) { s1 += vs; d1 += vd; }
        else if (t == 2) { s2 += vs; d2 += vd; }
        else { s3 += vs; d3 += vd; }
    }
    s0 = wredsum(s0); s1 = wredsum(s1); s2 = wredsum(s2); s3 = wredsum(s3);
    d0 = wredsum(d0); d1 = wredsum(d1); d2 = wredsum(d2); d3 = wredsum(d3);
    if (lane == 0) {
        as4[warp * 4 + 0] = s0; as4[warp * 4 + 1] = s1; as4[warp * 4 + 2] = s2; as4[warp * 4 + 3] = s3;
        ad4[warp * 4 + 0] = d0; ad4[warp * 4 + 1] = d1; ad4[warp * 4 + 2] = d2; ad4[warp * 4 + 3] = d3;
    }
}

// ---------------- fused task aggregation + log_softmax -> d_out ----------------
__global__ void gat_task(const float* __restrict__ Ht, const float* __restrict__ asv,
                         const float* __restrict__ adv, const int* __restrict__ rowp,
                         const int* __restrict__ col, const float* __restrict__ bias,
                         float* __restrict__ out, int n) {
    __shared__ float ws4[8][32][4];
    int wid = threadIdx.x >> 5, lane = threadIdx.x & 31;
    int node = blockIdx.x * 8 + wid;
    if (node >= n) return;
    float asn = 0.f, adn = 0.f;
    if (lane < 4) { asn = asv[node * 4 + lane]; adn = adv[node * 4 + lane]; }
    float m = lrelu(asn + adn);
    float adt[4], mt[4];
#pragma unroll
    for (int t = 0; t < 4; t++) {
        adt[t] = __shfl_sync(FULLM, adn, t);
        mt[t]  = __shfl_sync(FULLM, m, t);
    }
    float acc[7];
    int tk[7];
    const float* hself = Ht + (size_t)node * 224;
#pragma unroll
    for (int k = 0; k < 7; k++) {
        int c = lane + 32 * k;
        tk[k] = (c >= 12) + (c >= 42) + (c >= 102);
        acc[k] = hself[c];
    }
    float su0 = 0.f, su1 = 0.f, su2 = 0.f, su3 = 0.f;
    int beg = rowp[node], end = rowp[node + 1];
    for (int base = beg; base < end; base += 32) {
        int i = base + lane;
        int src_l = 0;
        float4 w4 = make_float4(0.f, 0.f, 0.f, 0.f);
        if (i < end) {
            src_l = col[i];
            float4 aq = *(const float4*)(asv + (size_t)src_l * 4);
            w4.x = __expf(lrelu(aq.x + adt[0]) - mt[0]);
            w4.y = __expf(lrelu(aq.y + adt[1]) - mt[1]);
            w4.z = __expf(lrelu(aq.z + adt[2]) - mt[2]);
            w4.w = __expf(lrelu(aq.w + adt[3]) - mt[3]);
            su0 += w4.x; su1 += w4.y; su2 += w4.z; su3 += w4.w;
        }
        *(float4*)&ws4[wid][lane][0] = w4;
        __syncwarp();
        int cnt = min(32, end - base);
#pragma unroll 2
        for (int e = 0; e < cnt; e++) {
            int se = __shfl_sync(FULLM, src_l, e);
            const float* hp = Ht + (size_t)se * 224;
#pragma unroll
            for (int k = 0; k < 7; k++)
                acc[k] = fmaf(ws4[wid][e][tk[k]], hp[lane + 32 * k], acc[k]);
        }
        __syncwarp();
    }
    float t0 = wredsum(su0) + 1.f + 1e-16f;
    float t1 = wredsum(su1) + 1.f + 1e-16f;
    float t2 = wredsum(su2) + 1.f + 1e-16f;
    float t3 = wredsum(su3) + 1.f + 1e-16f;
    float v[7];
#pragma unroll
    for (int k = 0; k < 7; k++) {
        float dk = (tk[k] == 0) ? t0 : (tk[k] == 1) ? t1 : (tk[k] == 2) ? t2 : t3;
        v[k] = acc[k] / dk + bias[lane + 32 * k];
    }
    const int Cc[4]  = {12, 30, 60, 120};
    const int Off[4] = {0, 12, 42, 102};
    size_t bases[4];
    bases[0] = 0; bases[1] = (size_t)n * 12; bases[2] = (size_t)n * 42; bases[3] = (size_t)n * 102;
#pragma unroll
    for (int t = 0; t < 4; t++) {
        float mx = -1e30f;
#pragma unroll
        for (int k = 0; k < 7; k++) { int c = lane + 32 * k; if (tk[k] == t && c < 222) mx = fmaxf(mx, v[k]); }
        mx = wredmax(mx);
        float se = 0.f;
#pragma unroll
        for (int k = 0; k < 7; k++) { int c = lane + 32 * k; if (tk[k] == t && c < 222) se += __expf(v[k] - mx); }
        se = wredsum(se);
        float lse = mx + __logf(se);
#pragma unroll
        for (int k = 0; k < 7; k++) {
            int c = lane + 32 * k;
            if (tk[k] == t && c < 222)
                out[bases[t] + (size_t)node * Cc[t] + (c - Off[t])] = v[k] - lse;
        }
    }
}

// ---------------- launch ----------------
extern "C" void kernel_launch(void* const* d_in, const int* in_sizes, int n_in,
                              void* d_out, int out_size) {
    const float* x   = (const float*)d_in[0];
    const int*   ei  = (const int*)d_in[1];
    const float* W1  = (const float*)d_in[2];
    const float* a1s = (const float*)d_in[3];
    const float* a1d = (const float*)d_in[4];
    const float* b1  = (const float*)d_in[5];
    const float* W2  = (const float*)d_in[6];
    const float* a2s = (const float*)d_in[7];
    const float* a2d = (const float*)d_in[8];
    const float* b2  = (const float*)d_in[9];
    const float* W_TL = (const float*)d_in[10], *as_TL = (const float*)d_in[11], *ad_TL = (const float*)d_in[12], *b_TL = (const float*)d_in[13];
    const float* W_YL = (const float*)d_in[14], *as_YL = (const float*)d_in[15], *ad_YL = (const float*)d_in[16], *b_YL = (const float*)d_in[17];
    const float* W_TS = (const float*)d_in[18], *as_TS = (const float*)d_in[19], *ad_TS = (const float*)d_in[20], *b_TS = (const float*)d_in[21];
    const float* W_TZ = (const float*)d_in[22], *as_TZ = (const float*)d_in[23], *ad_TZ = (const float*)d_in[24], *b_TZ = (const float*)d_in[25];

    int N = in_sizes[0] / 128;
    int E = in_sizes[1] / 2;

    float *bufA, *asv, *adv, *as4, *ad4, *acs, *acd, *bc;
    __nv_bfloat16 *xhi, *xlo, *hhi, *hlo, *B1hi, *B1lo, *B2hi, *B2lo, *Bthi, *Btlo;
    int *deg, *rowp, *cursor, *col;
    cudaGetSymbolAddress((void**)&bufA, g_bufA);
    cudaGetSymbolAddress((void**)&xhi, g_xhi);
    cudaGetSymbolAddress((void**)&xlo, g_xlo);
    cudaGetSymbolAddress((void**)&hhi, g_hhi);
    cudaGetSymbolAddress((void**)&hlo, g_hlo);
    cudaGetSymbolAddress((void**)&B1hi, g_B1hi);
    cudaGetSymbolAddress((void**)&B1lo, g_B1lo);
    cudaGetSymbolAddress((void**)&B2hi, g_B2hi);
    cudaGetSymbolAddress((void**)&B2lo, g_B2lo);
    cudaGetSymbolAddress((void**)&Bthi, g_Bthi);
    cudaGetSymbolAddress((void**)&Btlo, g_Btlo);
    cudaGetSymbolAddress((void**)&asv, g_as);
    cudaGetSymbolAddress((void**)&adv, g_ad);
    cudaGetSymbolAddress((void**)&as4, g_as4);
    cudaGetSymbolAddress((void**)&ad4, g_ad4);
    cudaGetSymbolAddress((void**)&acs, g_acs);
    cudaGetSymbolAddress((void**)&acd, g_acd);
    cudaGetSymbolAddress((void**)&bc, g_bc);
    cudaGetSymbolAddress((void**)&deg, g_deg);
    cudaGetSymbolAddress((void**)&rowp, g_rowp);
    cudaGetSymbolAddress((void**)&cursor, g_cursor);
    cudaGetSymbolAddress((void**)&col, g_col);

    int warpsGrid = (N + 7) / 8;
    int eGrid = (E + 255) / 256;
    dim3 gGemm(4, (N + 127) / 128);

    // 0: CSR zero
    zero_int<<<(N + 255) / 256, 256>>>(deg, N);
    // 1: x -> bf16 hi/lo
    convert_x<<<(N * 32 + 255) / 256, 256>>>(x, xhi, xlo, N);
    // 2: W1 pack (transposed bf16 hi/lo)
    pack_w<<<(256 * 128 + 255) / 256, 256>>>(W1, B1hi, B1lo, 128);
    // 3: conv1 GEMM (profiled launch)
    gemm_mma<<<gGemm, 256>>>(xhi, xlo, B1hi, B1lo, bufA, N, 128, 256,
                             a1s, a1d, asv, adv, 1);
    // 4-6: CSR
    count_deg<<<eGrid, 256>>>(ei, E, deg);
    scan_block<<<1, 1024>>>(deg, rowp, cursor, N);
    fill_col<<<eGrid, 256>>>(ei, E, cursor, col);
    // 7: W2 pack
    pack_w<<<(256 * 256 + 255) / 256, 256>>>(W2, B2hi, B2lo, 256);
    // 8: conv1 aggregation (+ELU) -> bf16 hi/lo
    gat_agg_conv<<<warpsGrid, 256>>>(bufA, asv, adv, rowp, col, b1, hhi, hlo, N, 1);
    // 9: conv2 GEMM
    gemm_mma<<<gGemm, 256>>>(hhi, hlo, B2hi, B2lo, bufA, N, 256, 256,
                             a2s, a2d, asv, adv, 1);
    // 10: task weight pack
    pack_wt<<<(256 * 256 + 255) / 256, 256>>>(W_TL, W_YL, W_TS, W_TZ,
                                              as_TL, as_YL, as_TS, as_TZ,
                                              ad_TL, ad_YL, ad_TS, ad_TZ,
                                              b_TL, b_YL, b_TS, b_TZ,
                                              Bthi, Btlo, acs, acd, bc);
    // 11: conv2 aggregation -> bf16 hi/lo
    gat_agg_conv<<<warpsGrid, 256>>>(bufA, asv, adv, rowp, col, b2, hhi, hlo, N, 0);
    // 12: task GEMM (Nout=224)
    gemm_mma<<<gGemm, 256>>>(hhi, hlo, Bthi, Btlo, bufA, N, 256, 224,
                             (const float*)0, (const float*)0,
                             (float*)0, (float*)0, 0);
    // 13-14: task alphas + fused aggregation/log-softmax
    alpha_task<<<warpsGrid, 256>>>(bufA, acs, acd, as4, ad4, N);
    gat_task<<<warpsGrid, 256>>>(bufA, as4, ad4, rowp, col, bc, (float*)d_out, N);
}

// round 7
// speedup vs baseline: 1.5869x; 1.0288x over previous
#include <cuda_runtime.h>
#include <cuda_bf16.h>
#include <math.h>
#include <stdint.h>

#define NN 50000
#define NROWPAD 50048
#define EE 800000
#define FULLM 0xffffffffu

// ---------------- static scratch (no allocation allowed) ----------------
__device__ __align__(128) float g_bufA[NROWPAD * 256];      // fp32 GEMM outputs
__device__ __align__(128) __nv_bfloat16 g_xhi[NROWPAD * 128];
__device__ __align__(128) __nv_bfloat16 g_xlo[NROWPAD * 128];
__device__ __align__(128) __nv_bfloat16 g_hhi[NROWPAD * 256];
__device__ __align__(128) __nv_bfloat16 g_hlo[NROWPAD * 256];
__device__ __align__(128) __nv_bfloat16 g_B1hi[256 * 128];
__device__ __align__(128) __nv_bfloat16 g_B1lo[256 * 128];
__device__ __align__(128) __nv_bfloat16 g_B2hi[256 * 256];
__device__ __align__(128) __nv_bfloat16 g_B2lo[256 * 256];
__device__ __align__(128) __nv_bfloat16 g_Bthi[256 * 256];
__device__ __align__(128) __nv_bfloat16 g_Btlo[256 * 256];
__device__ float g_as[NN * 8];
__device__ float g_ad[NN * 8];
__device__ float g_as4[NN * 4];
__device__ float g_ad4[NN * 4];
__device__ float g_acs[224];
__device__ float g_acd[224];
__device__ float g_bc[224];
__device__ int g_deg[NN];
__device__ int g_rowp[NN + 1];
__device__ int g_cursor[NN];
__device__ int g_col[EE];

// ---------------- helpers ----------------
__device__ __forceinline__ float wredsum(float v) {
#pragma unroll
    for (int o = 16; o > 0; o >>= 1) v += __shfl_xor_sync(FULLM, v, o);
    return v;
}
__device__ __forceinline__ float wredmax(float v) {
#pragma unroll
    for (int o = 16; o > 0; o >>= 1) v = fmaxf(v, __shfl_xor_sync(FULLM, v, o));
    return v;
}
__device__ __forceinline__ float lrelu(float e) { return e > 0.f ? e : 0.2f * e; }
__device__ __forceinline__ unsigned su32(const void* p) {
    unsigned r;
    asm("{ .reg .u64 t; cvta.to.shared.u64 t, %1; cvt.u32.u64 %0, t; }" : "=r"(r) : "l"(p));
    return r;
}
__device__ __forceinline__ void splitbf(float v, __nv_bfloat16& h, __nv_bfloat16& l) {
    h = __float2bfloat16(v);
    l = __float2bfloat16(v - __bfloat162float(h));
}
__device__ __forceinline__ uint32_t pkbf(__nv_bfloat16 a, __nv_bfloat16 b) {
    __nv_bfloat162 t(a, b);
    return *(uint32_t*)&t;
}
__device__ __forceinline__ void cpa16b(uint32_t dst, const void* src) {
    asm volatile("cp.async.ca.shared.global [%0], [%1], 16;" :: "r"(dst), "l"(src));
}
#define CPA_COMMIT() asm volatile("cp.async.commit_group;" ::: "memory")
#define CPA_WAIT1()  asm volatile("cp.async.wait_group 1;" ::: "memory")

__device__ __forceinline__ void ldmx4(uint32_t* r, uint32_t addr) {
    asm volatile("ldmatrix.sync.aligned.m8n8.x4.shared.b16 {%0,%1,%2,%3}, [%4];"
                 : "=r"(r[0]), "=r"(r[1]), "=r"(r[2]), "=r"(r[3]) : "r"(addr));
}
__device__ __forceinline__ void mma16816(float* c, const uint32_t* a,
                                         uint32_t b0, uint32_t b1) {
    asm volatile(
        "mma.sync.aligned.m16n8k16.row.col.f32.bf16.bf16.f32 "
        "{%0,%1,%2,%3}, {%4,%5,%6,%7}, {%8,%9}, {%0,%1,%2,%3};"
        : "+f"(c[0]), "+f"(c[1]), "+f"(c[2]), "+f"(c[3])
        : "r"(a[0]), "r"(a[1]), "r"(a[2]), "r"(a[3]), "r"(b0), "r"(b1));
}

// ---------------- CSR build ----------------
__global__ void zero_int(int* p, int n) {
    int i = blockIdx.x * blockDim.x + threadIdx.x;
    if (i < n) p[i] = 0;
}
__global__ void count_deg(const int* __restrict__ ei, int E, int* deg) {
    int e = blockIdx.x * blockDim.x + threadIdx.x;
    if (e < E) atomicAdd(&deg[ei[E + e]], 1);
}
__global__ void scan_block(const int* __restrict__ deg, int* __restrict__ rowp,
                           int* __restrict__ cursor, int n) {
    __shared__ int sm[1024];
    int tid = threadIdx.x;
    int chunk = (n + 1023) >> 10;
    int start = tid * chunk;
    int s = 0;
    for (int i = 0; i < chunk; i++) { int id = start + i; if (id < n) s += deg[id]; }
    sm[tid] = s; __syncthreads();
    for (int o = 1; o < 1024; o <<= 1) {
        int t = (tid >= o) ? sm[tid - o] : 0;
        __syncthreads();
        sm[tid] += t;
        __syncthreads();
    }
    int run = sm[tid] - s;
    for (int i = 0; i < chunk; i++) {
        int id = start + i;
        if (id < n) { rowp[id] = run; cursor[id] = run; run += deg[id]; }
    }
    if (tid == 1023) rowp[n] = sm[1023];
}
__global__ void fill_col(const int* __restrict__ ei, int E, int* cursor, int* __restrict__ col) {
    int e = blockIdx.x * blockDim.x + threadIdx.x;
    if (e < E) {
        int s = ei[e];
        int d = ei[E + e];
        int p = atomicAdd(&cursor[d], 1);
        col[p] = s;
    }
}

// ---------------- input conversion fp32 -> bf16 hi/lo ----------------
__global__ void convert_x(const float* __restrict__ x, __nv_bfloat16* __restrict__ xhi,
                          __nv_bfloat16* __restrict__ xlo, int n) {
    int idx = blockIdx.x * blockDim.x + threadIdx.x;   // 4 floats each
    if (idx >= n * 32) return;
    int row = idx >> 5, c4 = (idx & 31) << 2;
    float4 v = *(const float4*)(x + (size_t)row * 128 + c4);
    __nv_bfloat16 h0, l0, h1, l1, h2, l2, h3, l3;
    splitbf(v.x, h0, l0); splitbf(v.y, h1, l1);
    splitbf(v.z, h2, l2); splitbf(v.w, h3, l3);
    uint2 hw = make_uint2(pkbf(h0, h1), pkbf(h2, h3));
    uint2 lw = make_uint2(pkbf(l0, l1), pkbf(l2, l3));
    *(uint2*)(xhi + (size_t)row * 128 + c4) = hw;
    *(uint2*)(xlo + (size_t)row * 128 + c4) = lw;
}

// ---------------- weight packs: W[K][256] -> B[n][K] bf16 hi/lo (transposed) ----------
__global__ void pack_w(const float* __restrict__ W, __nv_bfloat16* __restrict__ bh,
                       __nv_bfloat16* __restrict__ bl, int K) {
    int idx = blockIdx.x * blockDim.x + threadIdx.x;
    if (idx >= 256 * K) return;
    int n = idx / K, k = idx % K;
    float v = W[(size_t)k * 256 + n];
    __nv_bfloat16 h, l;
    splitbf(v, h, l);
    bh[idx] = h; bl[idx] = l;
}
__global__ void pack_wt(const float* __restrict__ W0, const float* __restrict__ W1,
                        const float* __restrict__ W2, const float* __restrict__ W3,
                        const float* __restrict__ s0, const float* __restrict__ s1,
                        const float* __restrict__ s2, const float* __restrict__ s3,
                        const float* __restrict__ d0, const float* __restrict__ d1,
                        const float* __restrict__ d2, const float* __restrict__ d3,
                        const float* __restrict__ b0, const float* __restrict__ b1,
                        const float* __restrict__ b2, const float* __restrict__ b3,
                        __nv_bfloat16* __restrict__ bh, __nv_bfloat16* __restrict__ bl,
                        float* __restrict__ acs, float* __restrict__ acd,
                        float* __restrict__ bc) {
    int idx = blockIdx.x * blockDim.x + threadIdx.x;
    if (idx >= 256 * 256) return;
    int n = idx >> 8, k = idx & 255;
    float v = 0.f;
    if (n < 12) v = W0[k * 12 + n];
    else if (n < 42) v = W1[k * 30 + (n - 12)];
    else if (n < 102) v = W2[k * 60 + (n - 42)];
    else if (n < 222) v = W3[k * 120 + (n - 102)];
    __nv_bfloat16 h, l;
    splitbf(v, h, l);
    bh[idx] = h; bl[idx] = l;
    if (k == 0 && n < 224) {
        float s = 0.f, d = 0.f, b = 0.f;
        if (n < 12)       { s = s0[n];        d = d0[n];        b = b0[n]; }
        else if (n < 42)  { s = s1[n - 12];   d = d1[n - 12];   b = b1[n - 12]; }
        else if (n < 102) { s = s2[n - 42];   d = d2[n - 42];   b = b2[n - 42]; }
        else if (n < 222) { s = s3[n - 102];  d = d3[n - 102];  b = b3[n - 102]; }
        acs[n] = s; acd[n] = d; bc[n] = b;
    }
}

// ---------------- bf16x3 GEMM via mma.sync: C[M,Nout] = A[M,K] * W ----------------
// A bf16 hi/lo [Mpad,K]; B bf16 hi/lo [256,K] (row n = output col, K-major).
// CTA tile 128x128, warp tile 32x64 (4M x 2N warps), K chunk 16, cp.async dbl buffer.
// smem per stage (bf16 elems, row stride 24): AH 0, AL 3072, BH 6144, BL 9216.
__global__ __launch_bounds__(256, 2) void gemm_mma(
    const __nv_bfloat16* __restrict__ Ah, const __nv_bfloat16* __restrict__ Al,
    const __nv_bfloat16* __restrict__ Bh, const __nv_bfloat16* __restrict__ Bl,
    float* __restrict__ C, int M, int K, int Nout,
    const float* __restrict__ a_s, const float* __restrict__ a_d,
    float* __restrict__ as_out, float* __restrict__ ad_out, int do_alpha) {
    __shared__ __nv_bfloat16 smem[2][12288];
    int tid = threadIdx.x, wid = tid >> 5, lane = tid & 31;
    int rowBase = blockIdx.y * 128, colBase = blockIdx.x * 128;
    int warpM = (wid & 3) * 32, warpN = (wid >> 2) * 64;
    int g = lane >> 2, tg = lane & 3;

    float c[2][8][4];
#pragma unroll
    for (int mt = 0; mt < 2; mt++)
#pragma unroll
        for (int nt = 0; nt < 8; nt++)
#pragma unroll
            for (int j = 0; j < 4; j++) c[mt][nt][j] = 0.f;

    int arow = tid >> 1, ahalf = (tid & 1) * 8;
    uint32_t dstoff = (uint32_t)(arow * 24 + ahalf);

    auto issue = [&](int t, int buf) {
        int kc = t << 4;
        size_t aoff = (size_t)(rowBase + arow) * K + kc + ahalf;
        size_t boff = (size_t)(colBase + arow) * K + kc + ahalf;
        cpa16b(su32(&smem[buf][dstoff]), Ah + aoff);
        cpa16b(su32(&smem[buf][3072 + dstoff]), Al + aoff);
        cpa16b(su32(&smem[buf][6144 + dstoff]), Bh + boff);
        cpa16b(su32(&smem[buf][9216 + dstoff]), Bl + boff);
        CPA_COMMIT();
    };

    int T = K >> 4;
    issue(0, 0);
    for (int t = 0; t < T; t++) {
        if (t + 1 < T) issue(t + 1, (t + 1) & 1);
        else CPA_COMMIT();
        CPA_WAIT1();
        __syncthreads();
        uint32_t sb = su32(&smem[t & 1][0]);
        uint32_t aHi[2][4], aLo[2][4];
#pragma unroll
        for (int mt = 0; mt < 2; mt++) {
            uint32_t addr = sb + ((uint32_t)((warpM + mt * 16 + (lane & 15)) * 24
                                             + ((lane >> 4) & 1) * 8) << 1);
            ldmx4(aHi[mt], addr);
            ldmx4(aLo[mt], addr + 3072 * 2);
        }
#pragma unroll
        for (int nb = 0; nb < 4; nb++) {
            uint32_t bHi[4], bLo[4];
            uint32_t addr = sb + ((uint32_t)(6144
                              + (warpN + nb * 16 + (lane & 7) + ((lane >> 4) & 1) * 8) * 24
                              + ((lane >> 3) & 1) * 8) << 1);
            ldmx4(bHi, addr);
            ldmx4(bLo, addr + 3072 * 2);
#pragma unroll
            for (int mt = 0; mt < 2; mt++)
#pragma unroll
                for (int half = 0; half < 2; half++) {
                    int nt = nb * 2 + half, s = half * 2;
                    mma16816(c[mt][nt], aHi[mt], bHi[s], bHi[s + 1]);
                    mma16816(c[mt][nt], aHi[mt], bLo[s], bLo[s + 1]);
                    mma16816(c[mt][nt], aLo[mt], bHi[s], bHi[s + 1]);
                }
        }
        __syncthreads();
    }

    // store C (fp32)
#pragma unroll
    for (int mt = 0; mt < 2; mt++) {
        int r0 = rowBase + warpM + mt * 16 + g;
#pragma unroll
        for (int nt = 0; nt < 8; nt++) {
            int col = colBase + warpN + nt * 8 + tg * 2;
            if (col < Nout) {
                if (r0 < M)
                    *(float2*)(C + (size_t)r0 * Nout + col) = make_float2(c[mt][nt][0], c[mt][nt][1]);
                if (r0 + 8 < M)
                    *(float2*)(C + (size_t)(r0 + 8) * Nout + col) = make_float2(c[mt][nt][2], c[mt][nt][3]);
            }
        }
    }
    // fused per-head alpha (conv layers): warp tile 64 cols = 2 heads (32 cols each)
    if (do_alpha) {
#pragma unroll
        for (int hh = 0; hh < 2; hh++) {
            int head = ((colBase + warpN) >> 5) + hh;
#pragma unroll
            for (int mt = 0; mt < 2; mt++) {
                float sl = 0.f, sh = 0.f, dl = 0.f, dh = 0.f;
#pragma unroll
                for (int q = 0; q < 4; q++) {
                    int nt = hh * 4 + q;
                    int col = colBase + warpN + nt * 8 + tg * 2;
                    float s0 = a_s[col], s1 = a_s[col + 1];
                    float d0 = a_d[col], d1 = a_d[col + 1];
                    sl += c[mt][nt][0] * s0 + c[mt][nt][1] * s1;
                    sh += c[mt][nt][2] * s0 + c[mt][nt][3] * s1;
                    dl += c[mt][nt][0] * d0 + c[mt][nt][1] * d1;
                    dh += c[mt][nt][2] * d0 + c[mt][nt][3] * d1;
                }
                sl += __shfl_xor_sync(FULLM, sl, 1); sl += __shfl_xor_sync(FULLM, sl, 2);
                sh += __shfl_xor_sync(FULLM, sh, 1); sh += __shfl_xor_sync(FULLM, sh, 2);
                dl += __shfl_xor_sync(FULLM, dl, 1); dl += __shfl_xor_sync(FULLM, dl, 2);
                dh += __shfl_xor_sync(FULLM, dh, 1); dh += __shfl_xor_sync(FULLM, dh, 2);
                if (tg == 0) {
                    int r0 = rowBase + warpM + mt * 16 + g;
                    if (r0 < M)     { as_out[r0 * 8 + head] = sl;       ad_out[r0 * 8 + head] = dl; }
                    if (r0 + 8 < M) { as_out[(r0 + 8) * 8 + head] = sh; ad_out[(r0 + 8) * 8 + head] = dh; }
                }
            }
        }
    }
}

// ---------------- GAT aggregation (conv): outputs bf16 hi/lo for next GEMM ----------
__global__ void gat_agg_conv(const float* __restrict__ h, const float* __restrict__ asv,
                             const float* __restrict__ adv, const int* __restrict__ rowp,
                             const int* __restrict__ col, const float* __restrict__ bias,
                             __nv_bfloat16* __restrict__ outHi,
                             __nv_bfloat16* __restrict__ outLo, int n, int do_elu) {
    __shared__ float ws[8][32][8];
    int wid = threadIdx.x >> 5, lane = threadIdx.x & 31;
    int node = blockIdx.x * 8 + wid;
    if (node >= n) return;
    int head = lane >> 2;
    float asn = 0.f, adn = 0.f;
    if (lane < 8) { asn = asv[node * 8 + lane]; adn = adv[node * 8 + lane]; }
    float m = lrelu(asn + adn);               // shift (softmax invariant); w_self = 1
    float adh[8], mh[8];
#pragma unroll
    for (int k = 0; k < 8; k++) {
        adh[k] = __shfl_sync(FULLM, adn, k);
        mh[k]  = __shfl_sync(FULLM, m, k);
    }
    const float* hs0 = h + (size_t)node * 256 + lane * 8;
    float4 acc0 = *(const float4*)hs0;
    float4 acc1 = *(const float4*)(hs0 + 4);
    float ssum = 1.f;                          // self weight per head
    int beg = rowp[node], end = rowp[node + 1];
    for (int base = beg; base < end; base += 32) {
        int i = base + lane;
        int src_l = 0;
        float4 wlo = make_float4(0.f, 0.f, 0.f, 0.f), whi = wlo;
        if (i < end) {
            src_l = col[i];
            const float4* ap = (const float4*)(asv + (size_t)src_l * 8);
            float4 a0 = ap[0], a1 = ap[1];
            wlo.x = __expf(lrelu(a0.x + adh[0]) - mh[0]);
            wlo.y = __expf(lrelu(a0.y + adh[1]) - mh[1]);
            wlo.z = __expf(lrelu(a0.z + adh[2]) - mh[2]);
            wlo.w = __expf(lrelu(a0.w + adh[3]) - mh[3]);
            whi.x = __expf(lrelu(a1.x + adh[4]) - mh[4]);
            whi.y = __expf(lrelu(a1.y + adh[5]) - mh[5]);
            whi.z = __expf(lrelu(a1.z + adh[6]) - mh[6]);
            whi.w = __expf(lrelu(a1.w + adh[7]) - mh[7]);
        }
        *(float4*)&ws[wid][lane][0] = wlo;
        *(float4*)&ws[wid][lane][4] = whi;
        __syncwarp();
        int cnt = min(32, end - base);
#pragma unroll 4
        for (int e = 0; e < cnt; e++) {
            float we = ws[wid][e][head];
            int se = __shfl_sync(FULLM, src_l, e);
            ssum += we;
            const float* hp = h + (size_t)se * 256 + lane * 8;
            float4 v0 = *(const float4*)hp, v1 = *(const float4*)(hp + 4);
            acc0.x = fmaf(we, v0.x, acc0.x); acc0.y = fmaf(we, v0.y, acc0.y);
            acc0.z = fmaf(we, v0.z, acc0.z); acc0.w = fmaf(we, v0.w, acc0.w);
            acc1.x = fmaf(we, v1.x, acc1.x); acc1.y = fmaf(we, v1.y, acc1.y);
            acc1.z = fmaf(we, v1.z, acc1.z); acc1.w = fmaf(we, v1.w, acc1.w);
        }
        __syncwarp();
    }
    float inv = 1.f / (ssum + 1e-16f);
    const float* bp = bias + lane * 8;
    float4 b0 = *(const float4*)bp, b1v = *(const float4*)(bp + 4);
    float o[8];
    o[0] = acc0.x * inv + b0.x;  o[1] = acc0.y * inv + b0.y;
    o[2] = acc0.z * inv + b0.z;  o[3] = acc0.w * inv + b0.w;
    o[4] = acc1.x * inv + b1v.x; o[5] = acc1.y * inv + b1v.y;
    o[6] = acc1.z * inv + b1v.z; o[7] = acc1.w * inv + b1v.w;
    if (do_elu) {
#pragma unroll
        for (int j = 0; j < 8; j++) o[j] = o[j] > 0.f ? o[j] : expm1f(o[j]);
    }
    uint32_t hw[4], lw[4];
#pragma unroll
    for (int j = 0; j < 4; j++) {
        __nv_bfloat16 ha, la, hb, lb;
        splitbf(o[2 * j], ha, la);
        splitbf(o[2 * j + 1], hb, lb);
        hw[j] = pkbf(ha, hb);
        lw[j] = pkbf(la, lb);
    }
    size_t off = (size_t)node * 256 + lane * 8;
    *(uint4*)(outHi + off) = make_uint4(hw[0], hw[1], hw[2], hw[3]);
    *(uint4*)(outLo + off) = make_uint4(lw[0], lw[1], lw[2], lw[3]);
}

// ---------------- per-node attention scalars (4 task heads) ----------------
__global__ void alpha_task(const float* __restrict__ Ht, const float* __restrict__ acs,
                           const float* __restrict__ acd, float* __restrict__ as4,
                           float* __restrict__ ad4, int n) {
    int warp = (blockIdx.x * blockDim.x + threadIdx.x) >> 5;
    int lane = threadIdx.x & 31;
    if (warp >= n) return;
    const float* row = Ht + (size_t)warp * 224;
    float s0 = 0, s1 = 0, s2 = 0, s3 = 0, d0 = 0, d1 = 0, d2 = 0, d3 = 0;
#pragma unroll
    for (int k = 0; k < 7; k++) {
        int c = lane + 32 * k;
        float hv = row[c];
        float vs = hv * acs[c], vd = hv * acd[c];
        int t = (c >= 12) + (c >= 42) + (c >= 102);
        if (t == 0) { s0 += vs; d0 += vd; }
        else if (t == 1) { s1 += vs; d1 += vd; }
        else if (t == 2) { s2 += vs; d2 += vd; }
        else { s3 += vs; d3 += vd; }
    }
    s0 = wredsum(s0); s1 = wredsum(s1); s2 = wredsum(s2); s3 = wredsum(s3);
    d0 = wredsum(d0); d1 = wredsum(d1); d2 = wredsum(d2); d3 = wredsum(d3);
    if (lane == 0) {
        as4[warp * 4 + 0] = s0; as4[warp * 4 + 1] = s1; as4[warp * 4 + 2] = s2; as4[warp * 4 + 3] = s3;
        ad4[warp * 4 + 0] = d0; ad4[warp * 4 + 1] = d1; ad4[warp * 4 + 2] = d2; ad4[warp * 4 + 3] = d3;
    }
}

// ---------------- fused task aggregation + log_softmax -> d_out ----------------
__global__ void gat_task(const float* __restrict__ Ht, const float* __restrict__ asv,
                         const float* __restrict__ adv, const int* __restrict__ rowp,
                         const int* __restrict__ col, const float* __restrict__ bias,
                         float* __restrict__ out, int n) {
    __shared__ float ws4[8][32][4];
    int wid = threadIdx.x >> 5, lane = threadIdx.x & 31;
    int node = blockIdx.x * 8 + wid;
    if (node >= n) return;
    float asn = 0.f, adn = 0.f;
    if (lane < 4) { asn = asv[node * 4 + lane]; adn = adv[node * 4 + lane]; }
    float m = lrelu(asn + adn);
    float adt[4], mt[4];
#pragma unroll
    for (int t = 0; t < 4; t++) {
        adt[t] = __shfl_sync(FULLM, adn, t);
        mt[t]  = __shfl_sync(FULLM, m, t);
    }
    float acc[7];
    int tk[7];
    const float* hself = Ht + (size_t)node * 224;
#pragma unroll
    for (int k = 0; k < 7; k++) {
        int c = lane + 32 * k;
        tk[k] = (c >= 12) + (c >= 42) + (c >= 102);
        acc[k] = hself[c];
    }
    float su0 = 0.f, su1 = 0.f, su2 = 0.f, su3 = 0.f;
    int beg = rowp[node], end = rowp[node + 1];
    for (int base = beg; base < end; base += 32) {
        int i = base + lane;
        int src_l = 0;
        float4 w4 = make_float4(0.f, 0.f, 0.f, 0.f);
        if (i < end) {
            src_l = col[i];
            float4 aq = *(const float4*)(asv + (size_t)src_l * 4);
            w4.x = __expf(lrelu(aq.x + adt[0]) - mt[0]);
            w4.y = __expf(lrelu(aq.y + adt[1]) - mt[1]);
            w4.z = __expf(lrelu(aq.z + adt[2]) - mt[2]);
            w4.w = __expf(lrelu(aq.w + adt[3]) - mt[3]);
            su0 += w4.x; su1 += w4.y; su2 += w4.z; su3 += w4.w;
        }
        *(float4*)&ws4[wid][lane][0] = w4;
        __syncwarp();
        int cnt = min(32, end - base);
#pragma unroll 2
        for (int e = 0; e < cnt; e++) {
            int se = __shfl_sync(FULLM, src_l, e);
            const float* hp = Ht + (size_t)se * 224;
#pragma unroll
            for (int k = 0; k < 7; k++)
                acc[k] = fmaf(ws4[wid][e][tk[k]], hp[lane + 32 * k], acc[k]);
        }
        __syncwarp();
    }
    float t0 = wredsum(su0) + 1.f + 1e-16f;
    float t1 = wredsum(su1) + 1.f + 1e-16f;
    float t2 = wredsum(su2) + 1.f + 1e-16f;
    float t3 = wredsum(su3) + 1.f + 1e-16f;
    float v[7];
#pragma unroll
    for (int k = 0; k < 7; k++) {
        float dk = (tk[k] == 0) ? t0 : (tk[k] == 1) ? t1 : (tk[k] == 2) ? t2 : t3;
        v[k] = acc[k] / dk + bias[lane + 32 * k];
    }
    const int Cc[4]  = {12, 30, 60, 120};
    const int Off[4] = {0, 12, 42, 102};
    size_t bases[4];
    bases[0] = 0; bases[1] = (size_t)n * 12; bases[2] = (size_t)n * 42; bases[3] = (size_t)n * 102;
#pragma unroll
    for (int t = 0; t < 4; t++) {
        float mx = -1e30f;
#pragma unroll
        for (int k = 0; k < 7; k++) { int c = lane + 32 * k; if (tk[k] == t && c < 222) mx = fmaxf(mx, v[k]); }
        mx = wredmax(mx);
        float se = 0.f;
#pragma unroll
        for (int k = 0; k < 7; k++) { int c = lane + 32 * k; if (tk[k] == t && c < 222) se += __expf(v[k] - mx); }
        se = wredsum(se);
        float lse = mx + __logf(se);
#pragma unroll
        for (int k = 0; k < 7; k++) {
            int c = lane + 32 * k;
            if (tk[k] == t && c < 222)
                out[bases[t] + (size_t)node * Cc[t] + (c - Off[t])] = v[k] - lse;
        }
    }
}

// ---------------- launch ----------------
extern "C" void kernel_launch(void* const* d_in, const int* in_sizes, int n_in,
                              void* d_out, int out_size) {
    const float* x   = (const float*)d_in[0];
    const int*   ei  = (const int*)d_in[1];
    const float* W1  = (const float*)d_in[2];
    const float* a1s = (const float*)d_in[3];
    const float* a1d = (const float*)d_in[4];
    const float* b1  = (const float*)d_in[5];
    const float* W2  = (const float*)d_in[6];
    const float* a2s = (const float*)d_in[7];
    const float* a2d = (const float*)d_in[8];
    const float* b2  = (const float*)d_in[9];
    const float* W_TL = (const float*)d_in[10], *as_TL = (const float*)d_in[11], *ad_TL = (const float*)d_in[12], *b_TL = (const float*)d_in[13];
    const float* W_YL = (const float*)d_in[14], *as_YL = (const float*)d_in[15], *ad_YL = (const float*)d_in[16], *b_YL = (const float*)d_in[17];
    const float* W_TS = (const float*)d_in[18], *as_TS = (const float*)d_in[19], *ad_TS = (const float*)d_in[20], *b_TS = (const float*)d_in[21];
    const float* W_TZ = (const float*)d_in[22], *as_TZ = (const float*)d_in[23], *ad_TZ = (const float*)d_in[24], *b_TZ = (const float*)d_in[25];

    int N = in_sizes[0] / 128;
    int E = in_sizes[1] / 2;

    float *bufA, *asv, *adv, *as4, *ad4, *acs, *acd, *bc;
    __nv_bfloat16 *xhi, *xlo, *hhi, *hlo, *B1hi, *B1lo, *B2hi, *B2lo, *Bthi, *Btlo;
    int *deg, *rowp, *cursor, *col;
    cudaGetSymbolAddress((void**)&bufA, g_bufA);
    cudaGetSymbolAddress((void**)&xhi, g_xhi);
    cudaGetSymbolAddress((void**)&xlo, g_xlo);
    cudaGetSymbolAddress((void**)&hhi, g_hhi);
    cudaGetSymbolAddress((void**)&hlo, g_hlo);
    cudaGetSymbolAddress((void**)&B1hi, g_B1hi);
    cudaGetSymbolAddress((void**)&B1lo, g_B1lo);
    cudaGetSymbolAddress((void**)&B2hi, g_B2hi);
    cudaGetSymbolAddress((void**)&B2lo, g_B2lo);
    cudaGetSymbolAddress((void**)&Bthi, g_Bthi);
    cudaGetSymbolAddress((void**)&Btlo, g_Btlo);
    cudaGetSymbolAddress((void**)&asv, g_as);
    cudaGetSymbolAddress((void**)&adv, g_ad);
    cudaGetSymbolAddress((void**)&as4, g_as4);
    cudaGetSymbolAddress((void**)&ad4, g_ad4);
    cudaGetSymbolAddress((void**)&acs, g_acs);
    cudaGetSymbolAddress((void**)&acd, g_acd);
    cudaGetSymbolAddress((void**)&bc, g_bc);
    cudaGetSymbolAddress((void**)&deg, g_deg);
    cudaGetSymbolAddress((void**)&rowp, g_rowp);
    cudaGetSymbolAddress((void**)&cursor, g_cursor);
    cudaGetSymbolAddress((void**)&col, g_col);

    int warpsGrid = (N + 7) / 8;
    int eGrid = (E + 255) / 256;
    dim3 gGemm(2, (N + 127) / 128);

    // 0: CSR zero
    zero_int<<<(N + 255) / 256, 256>>>(deg, N);
    // 1: x -> bf16 hi/lo
    convert_x<<<(N * 32 + 255) / 256, 256>>>(x, xhi, xlo, N);
    // 2: W1 pack (transposed bf16 hi/lo)
    pack_w<<<(256 * 128 + 255) / 256, 256>>>(W1, B1hi, B1lo, 128);
    // 3: conv1 GEMM (profiled launch)
    gemm_mma<<<gGemm, 256>>>(xhi, xlo, B1hi, B1lo, bufA, N, 128, 256,
                             a1s, a1d, asv, adv, 1);
    // 4-6: CSR
    count_deg<<<eGrid, 256>>>(ei, E, deg);
    scan_block<<<1, 1024>>>(deg, rowp, cursor, N);
    fill_col<<<eGrid, 256>>>(ei, E, cursor, col);
    // 7: W2 pack
    pack_w<<<(256 * 256 + 255) / 256, 256>>>(W2, B2hi, B2lo, 256);
    // 8: conv1 aggregation (+ELU) -> bf16 hi/lo
    gat_agg_conv<<<warpsGrid, 256>>>(bufA, asv, adv, rowp, col, b1, hhi, hlo, N, 1);
    // 9: conv2 GEMM
    gemm_mma<<<gGemm, 256>>>(hhi, hlo, B2hi, B2lo, bufA, N, 256, 256,
                             a2s, a2d, asv, adv, 1);
    // 10: task weight pack
    pack_wt<<<(256 * 256 + 255) / 256, 256>>>(W_TL, W_YL, W_TS, W_TZ,
                                              as_TL, as_YL, as_TS, as_TZ,
                                              ad_TL, ad_YL, ad_TS, ad_TZ,
                                              b_TL, b_YL, b_TS, b_TZ,
                                              Bthi, Btlo, acs, acd, bc);
    // 11: conv2 aggregation -> bf16 hi/lo
    gat_agg_conv<<<warpsGrid, 256>>>(bufA, asv, adv, rowp, col, b2, hhi, hlo, N, 0);
    // 12: task GEMM (Nout=224)
    gemm_mma<<<gGemm, 256>>>(hhi, hlo, Bthi, Btlo, bufA, N, 256, 224,
                             (const float*)0, (const float*)0,
                             (float*)0, (float*)0, 0);
    // 13-14: task alphas + fused aggregation/log-softmax
    alpha_task<<<warpsGrid, 256>>>(bufA, acs, acd, as4, ad4, N);
    gat_task<<<warpsGrid, 256>>>(bufA, as4, ad4, rowp, col, bc, (float*)d_out, N);
}

// round 8
// speedup vs baseline: 1.6905x; 1.0653x over previous
#include <cuda_runtime.h>
#include <cuda_bf16.h>
#include <math.h>
#include <stdint.h>

#define NN 50000
#define NROWPAD 50048
#define EE 800000
#define FULLM 0xffffffffu

// ---------------- static scratch (no allocation allowed) ----------------
__device__ __align__(128) float g_bufA[NROWPAD * 256];      // fp32 GEMM outputs
__device__ __align__(128) __nv_bfloat16 g_xhi[NROWPAD * 128];
__device__ __align__(128) __nv_bfloat16 g_xlo[NROWPAD * 128];
__device__ __align__(128) __nv_bfloat16 g_hhi[NROWPAD * 256];
__device__ __align__(128) __nv_bfloat16 g_hlo[NROWPAD * 256];
__device__ __align__(128) __nv_bfloat16 g_B1hi[256 * 128];
__device__ __align__(128) __nv_bfloat16 g_B1lo[256 * 128];
__device__ __align__(128) __nv_bfloat16 g_B2hi[256 * 256];
__device__ __align__(128) __nv_bfloat16 g_B2lo[256 * 256];
__device__ __align__(128) __nv_bfloat16 g_Bthi[256 * 256];
__device__ __align__(128) __nv_bfloat16 g_Btlo[256 * 256];
__device__ float g_as[NN * 8];
__device__ float g_ad[NN * 8];
__device__ float g_as4[NN * 4];
__device__ float g_ad4[NN * 4];
__device__ float g_acs[224];
__device__ float g_acd[224];
__device__ float g_bc[224];
__device__ int g_deg[NN];
__device__ int g_rowp[NN + 1];
__device__ int g_cursor[NN];
__device__ int g_col[EE];

// ---------------- helpers ----------------
__device__ __forceinline__ float wredsum(float v) {
#pragma unroll
    for (int o = 16; o > 0; o >>= 1) v += __shfl_xor_sync(FULLM, v, o);
    return v;
}
__device__ __forceinline__ float wredmax(float v) {
#pragma unroll
    for (int o = 16; o > 0; o >>= 1) v = fmaxf(v, __shfl_xor_sync(FULLM, v, o));
    return v;
}
__device__ __forceinline__ float lrelu(float e) { return e > 0.f ? e : 0.2f * e; }
__device__ __forceinline__ unsigned su32(const void* p) {
    unsigned r;
    asm("{ .reg .u64 t; cvta.to.shared.u64 t, %1; cvt.u32.u64 %0, t; }" : "=r"(r) : "l"(p));
    return r;
}
__device__ __forceinline__ void splitbf(float v, __nv_bfloat16& h, __nv_bfloat16& l) {
    h = __float2bfloat16(v);
    l = __float2bfloat16(v - __bfloat162float(h));
}
__device__ __forceinline__ uint32_t pkbf(__nv_bfloat16 a, __nv_bfloat16 b) {
    __nv_bfloat162 t(a, b);
    return *(uint32_t*)&t;
}
__device__ __forceinline__ void cpa16b(uint32_t dst, const void* src) {
    asm volatile("cp.async.ca.shared.global [%0], [%1], 16;" :: "r"(dst), "l"(src));
}
#define CPA_COMMIT() asm volatile("cp.async.commit_group;" ::: "memory")
#define CPA_WAIT1()  asm volatile("cp.async.wait_group 1;" ::: "memory")

__device__ __forceinline__ void ldmx4(uint32_t* r, uint32_t addr) {
    asm volatile("ldmatrix.sync.aligned.m8n8.x4.shared.b16 {%0,%1,%2,%3}, [%4];"
                 : "=r"(r[0]), "=r"(r[1]), "=r"(r[2]), "=r"(r[3]) : "r"(addr));
}
__device__ __forceinline__ void mma16816(float* c, const uint32_t* a,
                                         uint32_t b0, uint32_t b1) {
    asm volatile(
        "mma.sync.aligned.m16n8k16.row.col.f32.bf16.bf16.f32 "
        "{%0,%1,%2,%3}, {%4,%5,%6,%7}, {%8,%9}, {%0,%1,%2,%3};"
        : "+f"(c[0]), "+f"(c[1]), "+f"(c[2]), "+f"(c[3])
        : "r"(a[0]), "r"(a[1]), "r"(a[2]), "r"(a[3]), "r"(b0), "r"(b1));
}

// ---------------- CSR build ----------------
__global__ void zero_int(int* p, int n) {
    int i = blockIdx.x * blockDim.x + threadIdx.x;
    if (i < n) p[i] = 0;
}
__global__ void count_deg(const int* __restrict__ ei, int E, int* deg) {
    int e = blockIdx.x * blockDim.x + threadIdx.x;
    if (e < E) atomicAdd(&deg[ei[E + e]], 1);
}
__global__ void scan_block(const int* __restrict__ deg, int* __restrict__ rowp,
                           int* __restrict__ cursor, int n) {
    __shared__ int sm[1024];
    int tid = threadIdx.x;
    int chunk = (n + 1023) >> 10;
    int start = tid * chunk;
    int s = 0;
    for (int i = 0; i < chunk; i++) { int id = start + i; if (id < n) s += deg[id]; }
    sm[tid] = s; __syncthreads();
    for (int o = 1; o < 1024; o <<= 1) {
        int t = (tid >= o) ? sm[tid - o] : 0;
        __syncthreads();
        sm[tid] += t;
        __syncthreads();
    }
    int run = sm[tid] - s;
    for (int i = 0; i < chunk; i++) {
        int id = start + i;
        if (id < n) { rowp[id] = run; cursor[id] = run; run += deg[id]; }
    }
    if (tid == 1023) rowp[n] = sm[1023];
}
__global__ void fill_col(const int* __restrict__ ei, int E, int* cursor, int* __restrict__ col) {
    int e = blockIdx.x * blockDim.x + threadIdx.x;
    if (e < E) {
        int s = ei[e];
        int d = ei[E + e];
        int p = atomicAdd(&cursor[d], 1);
        col[p] = s;
    }
}

// ---------------- input conversion fp32 -> bf16 hi/lo ----------------
__global__ void convert_x(const float* __restrict__ x, __nv_bfloat16* __restrict__ xhi,
                          __nv_bfloat16* __restrict__ xlo, int n) {
    int idx = blockIdx.x * blockDim.x + threadIdx.x;   // 4 floats each
    if (idx >= n * 32) return;
    int row = idx >> 5, c4 = (idx & 31) << 2;
    float4 v = *(const float4*)(x + (size_t)row * 128 + c4);
    __nv_bfloat16 h0, l0, h1, l1, h2, l2, h3, l3;
    splitbf(v.x, h0, l0); splitbf(v.y, h1, l1);
    splitbf(v.z, h2, l2); splitbf(v.w, h3, l3);
    uint2 hw = make_uint2(pkbf(h0, h1), pkbf(h2, h3));
    uint2 lw = make_uint2(pkbf(l0, l1), pkbf(l2, l3));
    *(uint2*)(xhi + (size_t)row * 128 + c4) = hw;
    *(uint2*)(xlo + (size_t)row * 128 + c4) = lw;
}

// ---------------- weight packs: W[K][256] -> B[n][K] bf16 hi/lo (transposed) ----------
__global__ void pack_w(const float* __restrict__ W, __nv_bfloat16* __restrict__ bh,
                       __nv_bfloat16* __restrict__ bl, int K) {
    int idx = blockIdx.x * blockDim.x + threadIdx.x;
    if (idx >= 256 * K) return;
    int n = idx / K, k = idx % K;
    float v = W[(size_t)k * 256 + n];
    __nv_bfloat16 h, l;
    splitbf(v, h, l);
    bh[idx] = h; bl[idx] = l;
}
__global__ void pack_wt(const float* __restrict__ W0, const float* __restrict__ W1,
                        const float* __restrict__ W2, const float* __restrict__ W3,
                        const float* __restrict__ s0, const float* __restrict__ s1,
                        const float* __restrict__ s2, const float* __restrict__ s3,
                        const float* __restrict__ d0, const float* __restrict__ d1,
                        const float* __restrict__ d2, const float* __restrict__ d3,
                        const float* __restrict__ b0, const float* __restrict__ b1,
                        const float* __restrict__ b2, const float* __restrict__ b3,
                        __nv_bfloat16* __restrict__ bh, __nv_bfloat16* __restrict__ bl,
                        float* __restrict__ acs, float* __restrict__ acd,
                        float* __restrict__ bc) {
    int idx = blockIdx.x * blockDim.x + threadIdx.x;
    if (idx >= 256 * 256) return;
    int n = idx >> 8, k = idx & 255;
    float v = 0.f;
    if (n < 12) v = W0[k * 12 + n];
    else if (n < 42) v = W1[k * 30 + (n - 12)];
    else if (n < 102) v = W2[k * 60 + (n - 42)];
    else if (n < 222) v = W3[k * 120 + (n - 102)];
    __nv_bfloat16 h, l;
    splitbf(v, h, l);
    bh[idx] = h; bl[idx] = l;
    if (k == 0 && n < 224) {
        float s = 0.f, d = 0.f, b = 0.f;
        if (n < 12)       { s = s0[n];        d = d0[n];        b = b0[n]; }
        else if (n < 42)  { s = s1[n - 12];   d = d1[n - 12];   b = b1[n - 12]; }
        else if (n < 102) { s = s2[n - 42];   d = d2[n - 42];   b = b2[n - 42]; }
        else if (n < 222) { s = s3[n - 102];  d = d3[n - 102];  b = b3[n - 102]; }
        acs[n] = s; acd[n] = d; bc[n] = b;
    }
}

// ---------------- bf16x3 GEMM via mma.sync: C[M,Nout] = A[M,K] * W ----------------
// A bf16 hi/lo [Mpad,K]; B bf16 hi/lo [256,K] (row n = output col, K-major).
// CTA tile 128x128, warp tile 32x64 (4M x 2N warps), K chunk 32, cp.async dbl buffer.
// Dynamic smem: 2 stages x 20480 bf16 (row stride 40 elems = 80B, conflict-free for
// ldmatrix since gcd(80,128)=16). Stage layout: AH 0, AL 5120, BH 10240, BL 15360.
#define STG_ELEMS 20480
#define SMEM_BYTES (2 * STG_ELEMS * 2)

__global__ __launch_bounds__(256, 2) void gemm_mma(
    const __nv_bfloat16* __restrict__ Ah, const __nv_bfloat16* __restrict__ Al,
    const __nv_bfloat16* __restrict__ Bh, const __nv_bfloat16* __restrict__ Bl,
    float* __restrict__ C, int M, int K, int Nout,
    const float* __restrict__ a_s, const float* __restrict__ a_d,
    float* __restrict__ as_out, float* __restrict__ ad_out, int do_alpha) {
    extern __shared__ __nv_bfloat16 smem[];
    int tid = threadIdx.x, wid = tid >> 5, lane = tid & 31;
    int rowBase = blockIdx.y * 128, colBase = blockIdx.x * 128;
    int warpM = (wid & 3) * 32, warpN = (wid >> 2) * 64;
    int g = lane >> 2, tg = lane & 3;

    float c[2][8][4];
#pragma unroll
    for (int mt = 0; mt < 2; mt++)
#pragma unroll
        for (int nt = 0; nt < 8; nt++)
#pragma unroll
            for (int j = 0; j < 4; j++) c[mt][nt][j] = 0.f;

    auto issue = [&](int t, int buf) {
        int kc = t << 5;
        uint32_t base = buf * STG_ELEMS;
#pragma unroll
        for (int i = 0; i < 2; i++) {
            int q = tid + i * 256;
            int r = q >> 2, seg = (q & 3) << 3;          // 4 x 8-elem segments per row
            size_t aoff = (size_t)(rowBase + r) * K + kc + seg;
            size_t boff = (size_t)(colBase + r) * K + kc + seg;
            uint32_t doff = base + (uint32_t)(r * 40 + seg);
            cpa16b(su32(&smem[doff]), Ah + aoff);
            cpa16b(su32(&smem[5120 + doff]), Al + aoff);
            cpa16b(su32(&smem[10240 + doff]), Bh + boff);
            cpa16b(su32(&smem[15360 + doff]), Bl + boff);
        }
        CPA_COMMIT();
    };

    int T = K >> 5;
    issue(0, 0);
    for (int t = 0; t < T; t++) {
        if (t + 1 < T) issue(t + 1, (t + 1) & 1);
        else CPA_COMMIT();
        CPA_WAIT1();
        __syncthreads();
        uint32_t sb = su32(&smem[(t & 1) * STG_ELEMS]);
#pragma unroll
        for (int ks = 0; ks < 32; ks += 16) {
            uint32_t aHi[2][4], aLo[2][4];
#pragma unroll
            for (int mt = 0; mt < 2; mt++) {
                uint32_t addr = sb + ((uint32_t)((warpM + mt * 16 + (lane & 15)) * 40
                                                 + ks + ((lane >> 4) & 1) * 8) << 1);
                ldmx4(aHi[mt], addr);
                ldmx4(aLo[mt], addr + 5120 * 2);
            }
#pragma unroll
            for (int nb = 0; nb < 4; nb++) {
                uint32_t bHi[4], bLo[4];
                uint32_t addr = sb + ((uint32_t)(10240
                                  + (warpN + nb * 16 + (lane & 7) + ((lane >> 4) & 1) * 8) * 40
                                  + ks + ((lane >> 3) & 1) * 8) << 1);
                ldmx4(bHi, addr);
                ldmx4(bLo, addr + 5120 * 2);
#pragma unroll
                for (int mt = 0; mt < 2; mt++)
#pragma unroll
                    for (int half = 0; half < 2; half++) {
                        int nt = nb * 2 + half, s = half * 2;
                        mma16816(c[mt][nt], aHi[mt], bHi[s], bHi[s + 1]);
                        mma16816(c[mt][nt], aHi[mt], bLo[s], bLo[s + 1]);
                        mma16816(c[mt][nt], aLo[mt], bHi[s], bHi[s + 1]);
                    }
            }
        }
        __syncthreads();
    }

    // store C (fp32)
#pragma unroll
    for (int mt = 0; mt < 2; mt++) {
        int r0 = rowBase + warpM + mt * 16 + g;
#pragma unroll
        for (int nt = 0; nt < 8; nt++) {
            int col = colBase + warpN + nt * 8 + tg * 2;
            if (col < Nout) {
                if (r0 < M)
                    *(float2*)(C + (size_t)r0 * Nout + col) = make_float2(c[mt][nt][0], c[mt][nt][1]);
                if (r0 + 8 < M)
                    *(float2*)(C + (size_t)(r0 + 8) * Nout + col) = make_float2(c[mt][nt][2], c[mt][nt][3]);
            }
        }
    }
    // fused per-head alpha (conv layers): warp tile 64 cols = 2 heads (32 cols each)
    if (do_alpha) {
#pragma unroll
        for (int hh = 0; hh < 2; hh++) {
            int head = ((colBase + warpN) >> 5) + hh;
#pragma unroll
            for (int mt = 0; mt < 2; mt++) {
                float sl = 0.f, sh = 0.f, dl = 0.f, dh = 0.f;
#pragma unroll
                for (int q = 0; q < 4; q++) {
                    int nt = hh * 4 + q;
                    int col = colBase + warpN + nt * 8 + tg * 2;
                    float s0 = a_s[col], s1 = a_s[col + 1];
                    float d0 = a_d[col], d1 = a_d[col + 1];
                    sl += c[mt][nt][0] * s0 + c[mt][nt][1] * s1;
                    sh += c[mt][nt][2] * s0 + c[mt][nt][3] * s1;
                    dl += c[mt][nt][0] * d0 + c[mt][nt][1] * d1;
                    dh += c[mt][nt][2] * d0 + c[mt][nt][3] * d1;
                }
                sl += __shfl_xor_sync(FULLM, sl, 1); sl += __shfl_xor_sync(FULLM, sl, 2);
                sh += __shfl_xor_sync(FULLM, sh, 1); sh += __shfl_xor_sync(FULLM, sh, 2);
                dl += __shfl_xor_sync(FULLM, dl, 1); dl += __shfl_xor_sync(FULLM, dl, 2);
                dh += __shfl_xor_sync(FULLM, dh, 1); dh += __shfl_xor_sync(FULLM, dh, 2);
                if (tg == 0) {
                    int r0 = rowBase + warpM + mt * 16 + g;
                    if (r0 < M)     { as_out[r0 * 8 + head] = sl;       ad_out[r0 * 8 + head] = dl; }
                    if (r0 + 8 < M) { as_out[(r0 + 8) * 8 + head] = sh; ad_out[(r0 + 8) * 8 + head] = dh; }
                }
            }
        }
    }
}

// ---------------- GAT aggregation (conv): outputs bf16 hi/lo for next GEMM ----------
__global__ void gat_agg_conv(const float* __restrict__ h, const float* __restrict__ asv,
                             const float* __restrict__ adv, const int* __restrict__ rowp,
                             const int* __restrict__ col, const float* __restrict__ bias,
                             __nv_bfloat16* __restrict__ outHi,
                             __nv_bfloat16* __restrict__ outLo, int n, int do_elu) {
    __shared__ float ws[8][32][8];
    int wid = threadIdx.x >> 5, lane = threadIdx.x & 31;
    int node = blockIdx.x * 8 + wid;
    if (node >= n) return;
    int head = lane >> 2;
    float asn = 0.f, adn = 0.f;
    if (lane < 8) { asn = asv[node * 8 + lane]; adn = adv[node * 8 + lane]; }
    float m = lrelu(asn + adn);               // shift (softmax invariant); w_self = 1
    float adh[8], mh[8];
#pragma unroll
    for (int k = 0; k < 8; k++) {
        adh[k] = __shfl_sync(FULLM, adn, k);
        mh[k]  = __shfl_sync(FULLM, m, k);
    }
    const float* hs0 = h + (size_t)node * 256 + lane * 8;
    float4 acc0 = *(const float4*)hs0;
    float4 acc1 = *(const float4*)(hs0 + 4);
    float ssum = 1.f;                          // self weight per head
    int beg = rowp[node], end = rowp[node + 1];
    for (int base = beg; base < end; base += 32) {
        int i = base + lane;
        int src_l = 0;
        float4 wlo = make_float4(0.f, 0.f, 0.f, 0.f), whi = wlo;
        if (i < end) {
            src_l = col[i];
            const float4* ap = (const float4*)(asv + (size_t)src_l * 8);
            float4 a0 = ap[0], a1 = ap[1];
            wlo.x = __expf(lrelu(a0.x + adh[0]) - mh[0]);
            wlo.y = __expf(lrelu(a0.y + adh[1]) - mh[1]);
            wlo.z = __expf(lrelu(a0.z + adh[2]) - mh[2]);
            wlo.w = __expf(lrelu(a0.w + adh[3]) - mh[3]);
            whi.x = __expf(lrelu(a1.x + adh[4]) - mh[4]);
            whi.y = __expf(lrelu(a1.y + adh[5]) - mh[5]);
            whi.z = __expf(lrelu(a1.z + adh[6]) - mh[6]);
            whi.w = __expf(lrelu(a1.w + adh[7]) - mh[7]);
        }
        *(float4*)&ws[wid][lane][0] = wlo;
        *(float4*)&ws[wid][lane][4] = whi;
        __syncwarp();
        int cnt = min(32, end - base);
#pragma unroll 4
        for (int e = 0; e < cnt; e++) {
            float we = ws[wid][e][head];
            int se = __shfl_sync(FULLM, src_l, e);
            ssum += we;
            const float* hp = h + (size_t)se * 256 + lane * 8;
            float4 v0 = *(const float4*)hp, v1 = *(const float4*)(hp + 4);
            acc0.x = fmaf(we, v0.x, acc0.x); acc0.y = fmaf(we, v0.y, acc0.y);
            acc0.z = fmaf(we, v0.z, acc0.z); acc0.w = fmaf(we, v0.w, acc0.w);
            acc1.x = fmaf(we, v1.x, acc1.x); acc1.y = fmaf(we, v1.y, acc1.y);
            acc1.z = fmaf(we, v1.z, acc1.z); acc1.w = fmaf(we, v1.w, acc1.w);
        }
        __syncwarp();
    }
    float inv = 1.f / (ssum + 1e-16f);
    const float* bp = bias + lane * 8;
    float4 b0 = *(const float4*)bp, b1v = *(const float4*)(bp + 4);
    float o[8];
    o[0] = acc0.x * inv + b0.x;  o[1] = acc0.y * inv + b0.y;
    o[2] = acc0.z * inv + b0.z;  o[3] = acc0.w * inv + b0.w;
    o[4] = acc1.x * inv + b1v.x; o[5] = acc1.y * inv + b1v.y;
    o[6] = acc1.z * inv + b1v.z; o[7] = acc1.w * inv + b1v.w;
    if (do_elu) {
#pragma unroll
        for (int j = 0; j < 8; j++) o[j] = o[j] > 0.f ? o[j] : expm1f(o[j]);
    }
    uint32_t hw[4], lw[4];
#pragma unroll
    for (int j = 0; j < 4; j++) {
        __nv_bfloat16 ha, la, hb, lb;
        splitbf(o[2 * j], ha, la);
        splitbf(o[2 * j + 1], hb, lb);
        hw[j] = pkbf(ha, hb);
        lw[j] = pkbf(la, lb);
    }
    size_t off = (size_t)node * 256 + lane * 8;
    *(uint4*)(outHi + off) = make_uint4(hw[0], hw[1], hw[2], hw[3]);
    *(uint4*)(outLo + off) = make_uint4(lw[0], lw[1], lw[2], lw[3]);
}

// ---------------- per-node attention scalars (4 task heads) ----------------
__global__ void alpha_task(const float* __restrict__ Ht, const float* __restrict__ acs,
                           const float* __restrict__ acd, float* __restrict__ as4,
                           float* __restrict__ ad4, int n) {
    int warp = (blockIdx.x * blockDim.x + threadIdx.x) >> 5;
    int lane = threadIdx.x & 31;
    if (warp >= n) return;
    const float* row = Ht + (size_t)warp * 224;
    float s0 = 0, s1 = 0, s2 = 0, s3 = 0, d0 = 0, d1 = 0, d2 = 0, d3 = 0;
#pragma unroll
    for (int k = 0; k < 7; k++) {
        int c = lane + 32 * k;
        float hv = row[c];
        float vs = hv * acs[c], vd = hv * acd[c];
        int t = (c >= 12) + (c >= 42) + (c >= 102);
        if (t == 0) { s0 += vs; d0 += vd; }
        else if (t == 1) { s1 += vs; d1 += vd; }
        else if (t == 2) { s2 += vs; d2 += vd; }
        else { s3 += vs; d3 += vd; }
    }
    s0 = wredsum(s0); s1 = wredsum(s1); s2 = wredsum(s2); s3 = wredsum(s3);
    d0 = wredsum(d0); d1 = wredsum(d1); d2 = wredsum(d2); d3 = wredsum(d3);
    if (lane == 0) {
        as4[warp * 4 + 0] = s0; as4[warp * 4 + 1] = s1; as4[warp * 4 + 2] = s2; as4[warp * 4 + 3] = s3;
        ad4[warp * 4 + 0] = d0; ad4[warp * 4 + 1] = d1; ad4[warp * 4 + 2] = d2; ad4[warp * 4 + 3] = d3;
    }
}

// ---------------- fused task aggregation + log_softmax -> d_out ----------------
__global__ void gat_task(const float* __restrict__ Ht, const float* __restrict__ asv,
                         const float* __restrict__ adv, const int* __restrict__ rowp,
                         const int* __restrict__ col, const float* __restrict__ bias,
                         float* __restrict__ out, int n) {
    __shared__ float ws4[8][32][4];
    int wid = threadIdx.x >> 5, lane = threadIdx.x & 31;
    int node = blockIdx.x * 8 + wid;
    if (node >= n) return;
    float asn = 0.f, adn = 0.f;
    if (lane < 4) { asn = asv[node * 4 + lane]; adn = adv[node * 4 + lane]; }
    float m = lrelu(asn + adn);
    float adt[4], mt[4];
#pragma unroll
    for (int t = 0; t < 4; t++) {
        adt[t] = __shfl_sync(FULLM, adn, t);
        mt[t]  = __shfl_sync(FULLM, m, t);
    }
    float acc[7];
    int tk[7];
    const float* hself = Ht + (size_t)node * 224;
#pragma unroll
    for (int k = 0; k < 7; k++) {
        int c = lane + 32 * k;
        tk[k] = (c >= 12) + (c >= 42) + (c >= 102);
        acc[k] = hself[c];
    }
    float su0 = 0.f, su1 = 0.f, su2 = 0.f, su3 = 0.f;
    int beg = rowp[node], end = rowp[node + 1];
    for (int base = beg; base < end; base += 32) {
        int i = base + lane;
        int src_l = 0;
        float4 w4 = make_float4(0.f, 0.f, 0.f, 0.f);
        if (i < end) {
            src_l = col[i];
            float4 aq = *(const float4*)(asv + (size_t)src_l * 4);
            w4.x = __expf(lrelu(aq.x + adt[0]) - mt[0]);
            w4.y = __expf(lrelu(aq.y + adt[1]) - mt[1]);
            w4.z = __expf(lrelu(aq.z + adt[2]) - mt[2]);
            w4.w = __expf(lrelu(aq.w + adt[3]) - mt[3]);
            su0 += w4.x; su1 += w4.y; su2 += w4.z; su3 += w4.w;
        }
        *(float4*)&ws4[wid][lane][0] = w4;
        __syncwarp();
        int cnt = min(32, end - base);
#pragma unroll 2
        for (int e = 0; e < cnt; e++) {
            int se = __shfl_sync(FULLM, src_l, e);
            const float* hp = Ht + (size_t)se * 224;
#pragma unroll
            for (int k = 0; k < 7; k++)
                acc[k] = fmaf(ws4[wid][e][tk[k]], hp[lane + 32 * k], acc[k]);
        }
        __syncwarp();
    }
    float t0 = wredsum(su0) + 1.f + 1e-16f;
    float t1 = wredsum(su1) + 1.f + 1e-16f;
    float t2 = wredsum(su2) + 1.f + 1e-16f;
    float t3 = wredsum(su3) + 1.f + 1e-16f;
    float v[7];
#pragma unroll
    for (int k = 0; k < 7; k++) {
        float dk = (tk[k] == 0) ? t0 : (tk[k] == 1) ? t1 : (tk[k] == 2) ? t2 : t3;
        v[k] = acc[k] / dk + bias[lane + 32 * k];
    }
    const int Cc[4]  = {12, 30, 60, 120};
    const int Off[4] = {0, 12, 42, 102};
    size_t bases[4];
    bases[0] = 0; bases[1] = (size_t)n * 12; bases[2] = (size_t)n * 42; bases[3] = (size_t)n * 102;
#pragma unroll
    for (int t = 0; t < 4; t++) {
        float mx = -1e30f;
#pragma unroll
        for (int k = 0; k < 7; k++) { int c = lane + 32 * k; if (tk[k] == t && c < 222) mx = fmaxf(mx, v[k]); }
        mx = wredmax(mx);
        float se = 0.f;
#pragma unroll
        for (int k = 0; k < 7; k++) { int c = lane + 32 * k; if (tk[k] == t && c < 222) se += __expf(v[k] - mx); }
        se = wredsum(se);
        float lse = mx + __logf(se);
#pragma unroll
        for (int k = 0; k < 7; k++) {
            int c = lane + 32 * k;
            if (tk[k] == t && c < 222)
                out[bases[t] + (size_t)node * Cc[t] + (c - Off[t])] = v[k] - lse;
        }
    }
}

// ---------------- launch ----------------
extern "C" void kernel_launch(void* const* d_in, const int* in_sizes, int n_in,
                              void* d_out, int out_size) {
    const float* x   = (const float*)d_in[0];
    const int*   ei  = (const int*)d_in[1];
    const float* W1  = (const float*)d_in[2];
    const float* a1s = (const float*)d_in[3];
    const float* a1d = (const float*)d_in[4];
    const float* b1  = (const float*)d_in[5];
    const float* W2  = (const float*)d_in[6];
    const float* a2s = (const float*)d_in[7];
    const float* a2d = (const float*)d_in[8];
    const float* b2  = (const float*)d_in[9];
    const float* W_TL = (const float*)d_in[10], *as_TL = (const float*)d_in[11], *ad_TL = (const float*)d_in[12], *b_TL = (const float*)d_in[13];
    const float* W_YL = (const float*)d_in[14], *as_YL = (const float*)d_in[15], *ad_YL = (const float*)d_in[16], *b_YL = (const float*)d_in[17];
    const float* W_TS = (const float*)d_in[18], *as_TS = (const float*)d_in[19], *ad_TS = (const float*)d_in[20], *b_TS = (const float*)d_in[21];
    const float* W_TZ = (const float*)d_in[22], *as_TZ = (const float*)d_in[23], *ad_TZ = (const float*)d_in[24], *b_TZ = (const float*)d_in[25];

    int N = in_sizes[0] / 128;
    int E = in_sizes[1] / 2;

    float *bufA, *asv, *adv, *as4, *ad4, *acs, *acd, *bc;
    __nv_bfloat16 *xhi, *xlo, *hhi, *hlo, *B1hi, *B1lo, *B2hi, *B2lo, *Bthi, *Btlo;
    int *deg, *rowp, *cursor, *col;
    cudaGetSymbolAddress((void**)&bufA, g_bufA);
    cudaGetSymbolAddress((void**)&xhi, g_xhi);
    cudaGetSymbolAddress((void**)&xlo, g_xlo);
    cudaGetSymbolAddress((void**)&hhi, g_hhi);
    cudaGetSymbolAddress((void**)&hlo, g_hlo);
    cudaGetSymbolAddress((void**)&B1hi, g_B1hi);
    cudaGetSymbolAddress((void**)&B1lo, g_B1lo);
    cudaGetSymbolAddress((void**)&B2hi, g_B2hi);
    cudaGetSymbolAddress((void**)&B2lo, g_B2lo);
    cudaGetSymbolAddress((void**)&Bthi, g_Bthi);
    cudaGetSymbolAddress((void**)&Btlo, g_Btlo);
    cudaGetSymbolAddress((void**)&asv, g_as);
    cudaGetSymbolAddress((void**)&adv, g_ad);
    cudaGetSymbolAddress((void**)&as4, g_as4);
    cudaGetSymbolAddress((void**)&ad4, g_ad4);
    cudaGetSymbolAddress((void**)&acs, g_acs);
    cudaGetSymbolAddress((void**)&acd, g_acd);
    cudaGetSymbolAddress((void**)&bc, g_bc);
    cudaGetSymbolAddress((void**)&deg, g_deg);
    cudaGetSymbolAddress((void**)&rowp, g_rowp);
    cudaGetSymbolAddress((void**)&cursor, g_cursor);
    cudaGetSymbolAddress((void**)&col, g_col);

    cudaFuncSetAttribute(gemm_mma, cudaFuncAttributeMaxDynamicSharedMemorySize, SMEM_BYTES);

    int warpsGrid = (N + 7) / 8;
    int eGrid = (E + 255) / 256;
    dim3 gGemm(2, (N + 127) / 128);

    // 0: CSR zero
    zero_int<<<(N + 255) / 256, 256>>>(deg, N);
    // 1: x -> bf16 hi/lo
    convert_x<<<(N * 32 + 255) / 256, 256>>>(x, xhi, xlo, N);
    // 2: W1 pack (transposed bf16 hi/lo)
    pack_w<<<(256 * 128 + 255) / 256, 256>>>(W1, B1hi, B1lo, 128);
    // 3: conv1 GEMM (profiled launch)
    gemm_mma<<<gGemm, 256, SMEM_BYTES>>>(xhi, xlo, B1hi, B1lo, bufA, N, 128, 256,
                                         a1s, a1d, asv, adv, 1);
    // 4-6: CSR
    count_deg<<<eGrid, 256>>>(ei, E, deg);
    scan_block<<<1, 1024>>>(deg, rowp, cursor, N);
    fill_col<<<eGrid, 256>>>(ei, E, cursor, col);
    // 7: W2 pack
    pack_w<<<(256 * 256 + 255) / 256, 256>>>(W2, B2hi, B2lo, 256);
    // 8: conv1 aggregation (+ELU) -> bf16 hi/lo
    gat_agg_conv<<<warpsGrid, 256>>>(bufA, asv, adv, rowp, col, b1, hhi, hlo, N, 1);
    // 9: conv2 GEMM
    gemm_mma<<<gGemm, 256, SMEM_BYTES>>>(hhi, hlo, B2hi, B2lo, bufA, N, 256, 256,
                                         a2s, a2d, asv, adv, 1);
    // 10: task weight pack
    pack_wt<<<(256 * 256 + 255) / 256, 256>>>(W_TL, W_YL, W_TS, W_TZ,
                                              as_TL, as_YL, as_TS, as_TZ,
                                              ad_TL, ad_YL, ad_TS, ad_TZ,
                                              b_TL, b_YL, b_TS, b_TZ,
                                              Bthi, Btlo, acs, acd, bc);
    // 11: conv2 aggregation -> bf16 hi/lo
    gat_agg_conv<<<warpsGrid, 256>>>(bufA, asv, adv, rowp, col, b2, hhi, hlo, N, 0);
    // 12: task GEMM (Nout=224)
    gemm_mma<<<gGemm, 256, SMEM_BYTES>>>(hhi, hlo, Bthi, Btlo, bufA, N, 256, 224,
                                         (const float*)0, (const float*)0,
                                         (float*)0, (float*)0, 0);
    // 13-14: task alphas + fused aggregation/log-softmax
    alpha_task<<<warpsGrid, 256>>>(bufA, acs, acd, as4, ad4, N);
    gat_task<<<warpsGrid, 256>>>(bufA, as4, ad4, rowp, col, bc, (float*)d_out, N);
}